// round 3
// baseline (speedup 1.0000x reference)
#include <cuda_runtime.h>
#include <math.h>

// ---------------- geometry ----------------
#define BB     32
#define CCH    3
#define IMG    224
#define PTCH   16
#define EE     768
#define NH     12
#define NL     12
#define NPR    16          // prompts per layer
#define NP     197
#define SS     213
#define HD     64
#define FFD    3072
#define EPSV   1e-6f
#define SCALEV 0.125f      // 1/sqrt(64)

#define BS      (BB * SS)          // 6816
#define NPATCH  196
#define MCONV   (BB * NPATCH)      // 6272
#define KPAD    225

// ---------------- scratch (device globals: allowed) ----------------
__device__ float g_h  [(size_t)BS * EE];
__device__ float g_hh [(size_t)BS * EE];
__device__ float g_qkv[(size_t)BS * 3 * EE];
__device__ float g_o  [(size_t)BS * EE];
__device__ float g_ff [(size_t)BS * FFD];

// ---------------- block reduce ----------------
__device__ __forceinline__ float blk_sum(float v) {
    __shared__ float red[8];
    __shared__ float tot;
    int lane = threadIdx.x & 31, w = threadIdx.x >> 5;
#pragma unroll
    for (int o = 16; o; o >>= 1) v += __shfl_xor_sync(0xffffffffu, v, o);
    if (lane == 0) red[w] = v;
    __syncthreads();
    if (w == 0) {
        float t = (lane < 8) ? red[lane] : 0.f;
#pragma unroll
        for (int o = 4; o; o >>= 1) t += __shfl_xor_sync(0xffffffffu, t, o);
        if (lane == 0) tot = t;
    }
    __syncthreads();
    return tot;
}

// ---------------- im2col for patch embedding ----------------
__global__ void im2col_kernel(const float* __restrict__ x, float* __restrict__ out) {
    int idx = blockIdx.x * 256 + threadIdx.x;
    if (idx >= MCONV * EE) return;
    int m = idx / EE;          // b*196 + p
    int k = idx % EE;          // c*256 + i*16 + j
    int b = m / NPATCH, p = m % NPATCH;
    int c = k >> 8, rem = k & 255, i = rem >> 4, j = rem & 15;
    int py = p / 14, px = p % 14;
    out[idx] = x[(((size_t)b * CCH + c) * IMG + (py * PTCH + i)) * IMG + (px * PTCH + j)];
}

// ---------------- generic SGEMM: C[M,N] = A[M,K] * W[N,K]^T + bias ----------------
// epi: 0 = bias only, 1 = bias + exact GELU, 2 = bias + residual (C preloaded)
__global__ __launch_bounds__(256, 2)
void sgemm_kernel(const float* __restrict__ A, const float* __restrict__ Bw,
                  const float* __restrict__ bias, float* __restrict__ C,
                  int M, int N, int K, int epi)
{
    __shared__ float As[8][128];
    __shared__ float Bs[8][128];
    const int tid  = threadIdx.x;
    const int row0 = blockIdx.y * 128;
    const int col0 = blockIdx.x * 128;
    const int lr = tid >> 1;
    const int lk = (tid & 1) * 4;
    const int tx = tid & 15;
    const int ty = tid >> 4;

    float acc[8][8];
#pragma unroll
    for (int i = 0; i < 8; i++)
#pragma unroll
        for (int j = 0; j < 8; j++) acc[i][j] = 0.f;

    const bool aval = (row0 + lr) < M;
    const bool bval = (col0 + lr) < N;
    const float* Aptr = A  + (size_t)(row0 + lr) * K + lk;
    const float* Bptr = Bw + (size_t)(col0 + lr) * K + lk;

    for (int k0 = 0; k0 < K; k0 += 8) {
        float4 av = make_float4(0.f, 0.f, 0.f, 0.f);
        float4 bv = make_float4(0.f, 0.f, 0.f, 0.f);
        if (aval) av = *(const float4*)(Aptr + k0);
        if (bval) bv = *(const float4*)(Bptr + k0);
        As[lk + 0][lr] = av.x; As[lk + 1][lr] = av.y;
        As[lk + 2][lr] = av.z; As[lk + 3][lr] = av.w;
        Bs[lk + 0][lr] = bv.x; Bs[lk + 1][lr] = bv.y;
        Bs[lk + 2][lr] = bv.z; Bs[lk + 3][lr] = bv.w;
        __syncthreads();
#pragma unroll
        for (int kk = 0; kk < 8; kk++) {
            float a[8], b[8];
            *(float4*)(a    ) = *(const float4*)&As[kk][ty * 8];
            *(float4*)(a + 4) = *(const float4*)&As[kk][ty * 8 + 4];
            *(float4*)(b    ) = *(const float4*)&Bs[kk][tx * 8];
            *(float4*)(b + 4) = *(const float4*)&Bs[kk][tx * 8 + 4];
#pragma unroll
            for (int i = 0; i < 8; i++)
#pragma unroll
                for (int j = 0; j < 8; j++)
                    acc[i][j] += a[i] * b[j];
        }
        __syncthreads();
    }

#pragma unroll
    for (int i = 0; i < 8; i++) {
        int r = row0 + ty * 8 + i;
        if (r >= M) break;
#pragma unroll
        for (int j = 0; j < 8; j++) {
            int c = col0 + tx * 8 + j;
            if (c >= N) continue;
            float v = acc[i][j] + bias[c];
            if (epi == 1) v = 0.5f * v * (1.f + erff(v * 0.70710678118654752f));
            size_t idx = (size_t)r * N + c;
            if (epi == 2) v += C[idx];
            C[idx] = v;
        }
    }
}

// ---------------- LN after cls/pos assembly (pre-transformer) ----------------
__global__ void lnpre_kernel(const float* __restrict__ conv, const float* __restrict__ cls,
                             const float* __restrict__ pos, const float* __restrict__ g,
                             const float* __restrict__ bb, float* __restrict__ dst)
{
    int row = blockIdx.x;              // b*NP + s
    int b = row / NP, s = row % NP;
    int t = threadIdx.x;
    const float* base = (s == 0) ? cls : conv + (size_t)(b * NPATCH + s - 1) * EE;
    const float* pr = pos + (size_t)s * EE;
    float x0 = base[t] + pr[t];
    float x1 = base[t + 256] + pr[t + 256];
    float x2 = base[t + 512] + pr[t + 512];
    float mean = blk_sum(x0 + x1 + x2) * (1.f / EE);
    float d0 = x0 - mean, d1 = x1 - mean, d2 = x2 - mean;
    float var = blk_sum(d0 * d0 + d1 * d1 + d2 * d2) * (1.f / EE);
    float rs = rsqrtf(var + EPSV);
    float* o = dst + (size_t)(b * SS + s) * EE;
    o[t]       = d0 * rs * g[t]       + bb[t];
    o[t + 256] = d1 * rs * g[t + 256] + bb[t + 256];
    o[t + 512] = d2 * rs * g[t + 512] + bb[t + 512];
}

// ---------------- LN1 with prompt substitution ----------------
// s < NP: LN(g_h row). s >= NP: take prompt row, write it into g_h (residual base), LN it.
__global__ void ln1_kernel(const float* __restrict__ src, const float* __restrict__ prompt,
                           const float* __restrict__ g, const float* __restrict__ bb,
                           float* __restrict__ hwr, float* __restrict__ dst)
{
    int row = blockIdx.x;              // b*SS + s
    int s = row % SS;
    int t = threadIdx.x;
    const float* in = (s < NP) ? src + (size_t)row * EE
                               : prompt + (size_t)(s - NP) * EE;
    float x0 = in[t], x1 = in[t + 256], x2 = in[t + 512];
    if (s >= NP) {
        float* hw = hwr + (size_t)row * EE;
        hw[t] = x0; hw[t + 256] = x1; hw[t + 512] = x2;
    }
    float mean = blk_sum(x0 + x1 + x2) * (1.f / EE);
    float d0 = x0 - mean, d1 = x1 - mean, d2 = x2 - mean;
    float var = blk_sum(d0 * d0 + d1 * d1 + d2 * d2) * (1.f / EE);
    float rs = rsqrtf(var + EPSV);
    float* o = dst + (size_t)row * EE;
    o[t]       = d0 * rs * g[t]       + bb[t];
    o[t + 256] = d1 * rs * g[t + 256] + bb[t + 256];
    o[t + 512] = d2 * rs * g[t + 512] + bb[t + 512];
}

// ---------------- plain LN (ln2) ----------------
__global__ void ln_kernel(const float* __restrict__ src, const float* __restrict__ g,
                          const float* __restrict__ bb, float* __restrict__ dst)
{
    int row = blockIdx.x;
    int t = threadIdx.x;
    const float* in = src + (size_t)row * EE;
    float x0 = in[t], x1 = in[t + 256], x2 = in[t + 512];
    float mean = blk_sum(x0 + x1 + x2) * (1.f / EE);
    float d0 = x0 - mean, d1 = x1 - mean, d2 = x2 - mean;
    float var = blk_sum(d0 * d0 + d1 * d1 + d2 * d2) * (1.f / EE);
    float rs = rsqrtf(var + EPSV);
    float* o = dst + (size_t)row * EE;
    o[t]       = d0 * rs * g[t]       + bb[t];
    o[t + 256] = d1 * rs * g[t + 256] + bb[t + 256];
    o[t + 512] = d2 * rs * g[t + 512] + bb[t + 512];
}

// ---------------- LN post (cls token only) ----------------
__global__ void lnpost_kernel(const float* __restrict__ src, const float* __restrict__ g,
                              const float* __restrict__ bb, float* __restrict__ dst)
{
    int b = blockIdx.x;
    int t = threadIdx.x;
    const float* in = src + (size_t)(b * SS) * EE;   // s = 0
    float x0 = in[t], x1 = in[t + 256], x2 = in[t + 512];
    float mean = blk_sum(x0 + x1 + x2) * (1.f / EE);
    float d0 = x0 - mean, d1 = x1 - mean, d2 = x2 - mean;
    float var = blk_sum(d0 * d0 + d1 * d1 + d2 * d2) * (1.f / EE);
    float rs = rsqrtf(var + EPSV);
    float* o = dst + (size_t)b * EE;
    o[t]       = d0 * rs * g[t]       + bb[t];
    o[t + 256] = d1 * rs * g[t + 256] + bb[t + 256];
    o[t + 512] = d2 * rs * g[t + 512] + bb[t + 512];
}

// ---------------- fused attention (one block per (b,h)) ----------------
// smem: Ks[64][KPAD] (K transposed), Vs[213][64], Ar[8][KPAD], Qs[8][64], Co[16]
#define SM_ATTN_FLOATS (64 * KPAD + SS * 64 + 8 * KPAD + 8 * 64 + 16)
__global__ void attn_kernel(const float* __restrict__ qkv,
                            const float* __restrict__ coeff,
                            float* __restrict__ outp)
{
    extern __shared__ float sm[];
    float* Ks = sm;
    float* Vs = Ks + 64 * KPAD;
    float* Ar = Vs + SS * 64;
    float* Qs = Ar + 8 * KPAD;
    float* Co = Qs + 8 * 64;

    const int bh = blockIdx.x;
    const int b = bh / NH, h = bh % NH;
    const int tid = threadIdx.x;
    const int w = tid >> 5, lane = tid & 31;
    const float* base = qkv + (size_t)b * SS * (3 * EE);

    for (int idx = tid; idx < SS * 64; idx += 256) {
        int s = idx >> 6, d = idx & 63;
        const float* row = base + (size_t)s * (3 * EE) + h * HD;
        Ks[d * KPAD + s] = row[EE + d];
        Vs[idx]          = row[2 * EE + d];
    }
    if (tid < NPR) Co[tid] = coeff[tid];
    __syncthreads();

    for (int q = w; q < SS; q += 8) {
        const float* qrow = base + (size_t)q * (3 * EE) + h * HD;
        Qs[w * 64 + lane]      = qrow[lane];
        Qs[w * 64 + lane + 32] = qrow[lane + 32];
        __syncwarp();

        float sc[7];
#pragma unroll
        for (int i = 0; i < 7; i++) sc[i] = 0.f;
#pragma unroll 8
        for (int d = 0; d < 64; d++) {
            float qd = Qs[w * 64 + d];
#pragma unroll
            for (int i = 0; i < 7; i++)
                sc[i] += qd * Ks[d * KPAD + lane + 32 * i];
        }

        float m = -INFINITY;
#pragma unroll
        for (int i = 0; i < 7; i++) {
            int k = lane + 32 * i;
            if (k < SS) {
                float v = sc[i] * SCALEV;
                if (k >= NP) v *= Co[k - NP];
                sc[i] = v;
                m = fmaxf(m, v);
            } else sc[i] = -INFINITY;
        }
#pragma unroll
        for (int o = 16; o; o >>= 1) m = fmaxf(m, __shfl_xor_sync(0xffffffffu, m, o));

        float ssum = 0.f;
#pragma unroll
        for (int i = 0; i < 7; i++) {
            int k = lane + 32 * i;
            float p = __expf(sc[i] - m);
            if (k < SS) { ssum += p; Ar[w * KPAD + k] = p; }
        }
#pragma unroll
        for (int o = 16; o; o >>= 1) ssum += __shfl_xor_sync(0xffffffffu, ssum, o);
        __syncwarp();

        float o1 = 0.f, o2 = 0.f;
        for (int k = 0; k < SS; k++) {
            float a = Ar[w * KPAD + k];
            o1 += a * Vs[k * 64 + lane];
            o2 += a * Vs[k * 64 + lane + 32];
        }
        float inv = 1.f / ssum;
        float* orow = outp + (size_t)(b * SS + q) * EE + h * HD;
        orow[lane]      = o1 * inv;
        orow[lane + 32] = o2 * inv;
        __syncwarp();
    }
}

// ---------------- host launch ----------------
extern "C" void kernel_launch(void* const* d_in, const int* in_sizes, int n_in,
                              void* d_out, int out_size)
{
    const float* x        = (const float*)d_in[0];
    const float* coeff    = (const float*)d_in[1];
    const float* patch_w  = (const float*)d_in[2];
    const float* patch_b  = (const float*)d_in[3];
    const float* cls      = (const float*)d_in[4];
    const float* pos      = (const float*)d_in[5];
    const float* lnpre_g  = (const float*)d_in[6];
    const float* lnpre_b  = (const float*)d_in[7];
    const float* prompts  = (const float*)d_in[8];
    const float* ln1_g    = (const float*)d_in[9];
    const float* ln1_b    = (const float*)d_in[10];
    const float* qkv_w    = (const float*)d_in[11];
    const float* qkv_b    = (const float*)d_in[12];
    const float* proj_w   = (const float*)d_in[13];
    const float* proj_b   = (const float*)d_in[14];
    const float* ln2_g    = (const float*)d_in[15];
    const float* ln2_b    = (const float*)d_in[16];
    const float* fc1_w    = (const float*)d_in[17];
    const float* fc1_b    = (const float*)d_in[18];
    const float* fc2_w    = (const float*)d_in[19];
    const float* fc2_b    = (const float*)d_in[20];
    const float* lnpost_g = (const float*)d_in[21];
    const float* lnpost_b = (const float*)d_in[22];
    float* out = (float*)d_out;

    float *p_h, *p_hh, *p_qkv, *p_o, *p_ff;
    cudaGetSymbolAddress((void**)&p_h,  g_h);
    cudaGetSymbolAddress((void**)&p_hh, g_hh);
    cudaGetSymbolAddress((void**)&p_qkv, g_qkv);
    cudaGetSymbolAddress((void**)&p_o,  g_o);
    cudaGetSymbolAddress((void**)&p_ff, g_ff);

    const int smAttn = SM_ATTN_FLOATS * (int)sizeof(float);
    cudaFuncSetAttribute(attn_kernel, cudaFuncAttributeMaxDynamicSharedMemorySize, smAttn);

    // patch embedding: im2col -> GEMM -> compact conv output in p_o
    im2col_kernel<<<(MCONV * EE + 255) / 256, 256>>>(x, p_ff);
    sgemm_kernel<<<dim3(EE / 128, (MCONV + 127) / 128), 256>>>(
        p_ff, patch_w, patch_b, p_o, MCONV, EE, EE, 0);

    // cls + pos + ln_pre -> g_h (197 tokens per batch; prompt slots set per-layer)
    lnpre_kernel<<<BB * NP, 256>>>(p_o, cls, pos, lnpre_g, lnpre_b, p_h);

    const int mt = (BS + 127) / 128;   // 54
    for (int l = 0; l < NL; l++) {
        ln1_kernel<<<BS, 256>>>(p_h, prompts + (size_t)l * NPR * EE,
                                ln1_g + l * EE, ln1_b + l * EE, p_h, p_hh);
        sgemm_kernel<<<dim3(3 * EE / 128, mt), 256>>>(
            p_hh, qkv_w + (size_t)l * 3 * EE * EE, qkv_b + (size_t)l * 3 * EE,
            p_qkv, BS, 3 * EE, EE, 0);
        attn_kernel<<<BB * NH, 256, smAttn>>>(p_qkv, coeff + (size_t)l * NPR, p_o);
        sgemm_kernel<<<dim3(EE / 128, mt), 256>>>(
            p_o, proj_w + (size_t)l * EE * EE, proj_b + (size_t)l * EE,
            p_h, BS, EE, EE, 2);
        ln_kernel<<<BS, 256>>>(p_h, ln2_g + l * EE, ln2_b + l * EE, p_hh);
        sgemm_kernel<<<dim3(FFD / 128, mt), 256>>>(
            p_hh, fc1_w + (size_t)l * FFD * EE, fc1_b + (size_t)l * FFD,
            p_ff, BS, FFD, EE, 1);
        sgemm_kernel<<<dim3(EE / 128, mt), 256>>>(
            p_ff, fc2_w + (size_t)l * EE * FFD, fc2_b + (size_t)l * EE,
            p_h, BS, EE, FFD, 2);
    }

    lnpost_kernel<<<BB, 256>>>(p_h, lnpost_g, lnpost_b, out);
}

// round 4
// speedup vs baseline: 2.3955x; 2.3955x over previous
#include <cuda_runtime.h>
#include <math.h>
#include <stdint.h>

// ---------------- geometry ----------------
#define BB     32
#define CCH    3
#define IMG    224
#define PTCH   16
#define EE     768
#define NH     12
#define NL     12
#define NPR    16          // prompts per layer
#define NP     197
#define SS     213
#define HD     64
#define FFD    3072
#define EPSV   1e-6f
#define SCALEV 0.125f      // 1/sqrt(64)

#define BS      (BB * SS)          // 6816
#define NPATCH  196
#define MCONV   (BB * NPATCH)      // 6272
#define KPAD    225

// ---------------- scratch (device globals: allowed) ----------------
__device__ float g_h  [(size_t)BS * EE];
__device__ float g_hh [(size_t)BS * EE];
__device__ float g_qkv[(size_t)BS * 3 * EE];
__device__ float g_o  [(size_t)BS * EE];
__device__ float g_ff [(size_t)BS * FFD];

// ---------------- helpers ----------------
__device__ __forceinline__ float blk_sum(float v) {
    __shared__ float red[8];
    __shared__ float tot;
    int lane = threadIdx.x & 31, w = threadIdx.x >> 5;
#pragma unroll
    for (int o = 16; o; o >>= 1) v += __shfl_xor_sync(0xffffffffu, v, o);
    if (lane == 0) red[w] = v;
    __syncthreads();
    if (w == 0) {
        float t = (lane < 8) ? red[lane] : 0.f;
#pragma unroll
        for (int o = 4; o; o >>= 1) t += __shfl_xor_sync(0xffffffffu, t, o);
        if (lane == 0) tot = t;
    }
    __syncthreads();
    return tot;
}

__device__ __forceinline__ float tf32r(float f) {
    uint32_t u;
    asm("cvt.rna.tf32.f32 %0, %1;" : "=r"(u) : "f"(f));
    return __uint_as_float(u);
}

// ---------------- im2col for patch embedding ----------------
__global__ void im2col_kernel(const float* __restrict__ x, float* __restrict__ out) {
    int idx = blockIdx.x * 256 + threadIdx.x;
    if (idx >= MCONV * EE) return;
    int m = idx / EE;          // b*196 + p
    int k = idx % EE;          // c*256 + i*16 + j
    int b = m / NPATCH, p = m % NPATCH;
    int c = k >> 8, rem = k & 255, i = rem >> 4, j = rem & 15;
    int py = p / 14, px = p % 14;
    out[idx] = x[(((size_t)b * CCH + c) * IMG + (py * PTCH + i)) * IMG + (px * PTCH + j)];
}

// ---------------- TF32 tensor-core GEMM: C[M,N] = A[M,K] * W[N,K]^T + bias ----
// epi: 0 = bias only, 1 = bias + exact GELU, 2 = bias + residual (C preloaded)
// block tile 128x128, 8 warps (2 M x 4 N), warp tile 64x32, K-tile 32
#define SMPAD 36
__global__ __launch_bounds__(256)
void tgemm_kernel(const float* __restrict__ A, const float* __restrict__ Bw,
                  const float* __restrict__ bias, float* __restrict__ C,
                  int M, int N, int K, int epi)
{
    __shared__ float As[128][SMPAD];
    __shared__ float Bs[128][SMPAD];

    const int tid  = threadIdx.x;
    const int warp = tid >> 5, lane = tid & 31;
    const int wm = warp >> 2;            // 0..1
    const int wn = warp & 3;             // 0..3
    const int r  = lane >> 2;            // 0..7
    const int cg = lane & 3;             // 0..3
    const int row0 = blockIdx.y * 128;
    const int col0 = blockIdx.x * 128;

    float acc[4][4][4];
#pragma unroll
    for (int mi = 0; mi < 4; mi++)
#pragma unroll
        for (int ni = 0; ni < 4; ni++)
#pragma unroll
            for (int e = 0; e < 4; e++) acc[mi][ni][e] = 0.f;

    const int lrow = tid >> 1;
    const int lk   = (tid & 1) * 16;
    const bool aval = (row0 + lrow) < M;
    const float* Aptr = A  + (size_t)(row0 + lrow) * K + lk;
    const float* Bptr = Bw + (size_t)(col0 + lrow) * K + lk;

    for (int k0 = 0; k0 < K; k0 += 32) {
#pragma unroll
        for (int i = 0; i < 4; i++) {
            float4 av = make_float4(0.f, 0.f, 0.f, 0.f);
            if (aval) av = *(const float4*)(Aptr + k0 + 4 * i);
            float4 bv = *(const float4*)(Bptr + k0 + 4 * i);
            As[lrow][lk + 4 * i + 0] = tf32r(av.x);
            As[lrow][lk + 4 * i + 1] = tf32r(av.y);
            As[lrow][lk + 4 * i + 2] = tf32r(av.z);
            As[lrow][lk + 4 * i + 3] = tf32r(av.w);
            Bs[lrow][lk + 4 * i + 0] = tf32r(bv.x);
            Bs[lrow][lk + 4 * i + 1] = tf32r(bv.y);
            Bs[lrow][lk + 4 * i + 2] = tf32r(bv.z);
            Bs[lrow][lk + 4 * i + 3] = tf32r(bv.w);
        }
        __syncthreads();

#pragma unroll
        for (int kk = 0; kk < 32; kk += 8) {
            uint32_t af[4][4], bf[4][2];
#pragma unroll
            for (int mi = 0; mi < 4; mi++) {
                int mr = wm * 64 + mi * 16;
                af[mi][0] = __float_as_uint(As[mr + r    ][kk + cg    ]);
                af[mi][1] = __float_as_uint(As[mr + r + 8][kk + cg    ]);
                af[mi][2] = __float_as_uint(As[mr + r    ][kk + cg + 4]);
                af[mi][3] = __float_as_uint(As[mr + r + 8][kk + cg + 4]);
            }
#pragma unroll
            for (int ni = 0; ni < 4; ni++) {
                int nc = wn * 32 + ni * 8;
                bf[ni][0] = __float_as_uint(Bs[nc + r][kk + cg    ]);
                bf[ni][1] = __float_as_uint(Bs[nc + r][kk + cg + 4]);
            }
#pragma unroll
            for (int mi = 0; mi < 4; mi++)
#pragma unroll
                for (int ni = 0; ni < 4; ni++) {
                    asm volatile(
                        "mma.sync.aligned.m16n8k8.row.col.f32.tf32.tf32.f32 "
                        "{%0,%1,%2,%3}, {%4,%5,%6,%7}, {%8,%9}, {%0,%1,%2,%3};"
                        : "+f"(acc[mi][ni][0]), "+f"(acc[mi][ni][1]),
                          "+f"(acc[mi][ni][2]), "+f"(acc[mi][ni][3])
                        : "r"(af[mi][0]), "r"(af[mi][1]), "r"(af[mi][2]), "r"(af[mi][3]),
                          "r"(bf[ni][0]), "r"(bf[ni][1]));
                }
        }
        __syncthreads();
    }

    // epilogue
#pragma unroll
    for (int mi = 0; mi < 4; mi++) {
        int mr0 = row0 + wm * 64 + mi * 16 + r;
#pragma unroll
        for (int ni = 0; ni < 4; ni++) {
            int nc = col0 + wn * 32 + ni * 8 + 2 * cg;
            float b0 = bias[nc], b1 = bias[nc + 1];
#pragma unroll
            for (int half = 0; half < 2; half++) {
                int rr = mr0 + half * 8;
                if (rr >= M) continue;
                float v0 = acc[mi][ni][half * 2 + 0] + b0;
                float v1 = acc[mi][ni][half * 2 + 1] + b1;
                if (epi == 1) {
                    v0 = 0.5f * v0 * (1.f + erff(v0 * 0.70710678118654752f));
                    v1 = 0.5f * v1 * (1.f + erff(v1 * 0.70710678118654752f));
                }
                size_t idx = (size_t)rr * N + nc;
                if (epi == 2) { v0 += C[idx]; v1 += C[idx + 1]; }
                C[idx] = v0; C[idx + 1] = v1;
            }
        }
    }
}

// ---------------- LN after cls/pos assembly (pre-transformer) ----------------
__global__ void lnpre_kernel(const float* __restrict__ conv, const float* __restrict__ cls,
                             const float* __restrict__ pos, const float* __restrict__ g,
                             const float* __restrict__ bb, float* __restrict__ dst)
{
    int row = blockIdx.x;              // b*NP + s
    int b = row / NP, s = row % NP;
    int t = threadIdx.x;
    const float* base = (s == 0) ? cls : conv + (size_t)(b * NPATCH + s - 1) * EE;
    const float* pr = pos + (size_t)s * EE;
    float x0 = base[t] + pr[t];
    float x1 = base[t + 256] + pr[t + 256];
    float x2 = base[t + 512] + pr[t + 512];
    float mean = blk_sum(x0 + x1 + x2) * (1.f / EE);
    float d0 = x0 - mean, d1 = x1 - mean, d2 = x2 - mean;
    float var = blk_sum(d0 * d0 + d1 * d1 + d2 * d2) * (1.f / EE);
    float rs = rsqrtf(var + EPSV);
    float* o = dst + (size_t)(b * SS + s) * EE;
    o[t]       = d0 * rs * g[t]       + bb[t];
    o[t + 256] = d1 * rs * g[t + 256] + bb[t + 256];
    o[t + 512] = d2 * rs * g[t + 512] + bb[t + 512];
}

// ---------------- LN1 with prompt substitution ----------------
__global__ void ln1_kernel(const float* __restrict__ src, const float* __restrict__ prompt,
                           const float* __restrict__ g, const float* __restrict__ bb,
                           float* __restrict__ hwr, float* __restrict__ dst)
{
    int row = blockIdx.x;              // b*SS + s
    int s = row % SS;
    int t = threadIdx.x;
    const float* in = (s < NP) ? src + (size_t)row * EE
                               : prompt + (size_t)(s - NP) * EE;
    float x0 = in[t], x1 = in[t + 256], x2 = in[t + 512];
    if (s >= NP) {
        float* hw = hwr + (size_t)row * EE;
        hw[t] = x0; hw[t + 256] = x1; hw[t + 512] = x2;
    }
    float mean = blk_sum(x0 + x1 + x2) * (1.f / EE);
    float d0 = x0 - mean, d1 = x1 - mean, d2 = x2 - mean;
    float var = blk_sum(d0 * d0 + d1 * d1 + d2 * d2) * (1.f / EE);
    float rs = rsqrtf(var + EPSV);
    float* o = dst + (size_t)row * EE;
    o[t]       = d0 * rs * g[t]       + bb[t];
    o[t + 256] = d1 * rs * g[t + 256] + bb[t + 256];
    o[t + 512] = d2 * rs * g[t + 512] + bb[t + 512];
}

// ---------------- plain LN (ln2) ----------------
__global__ void ln_kernel(const float* __restrict__ src, const float* __restrict__ g,
                          const float* __restrict__ bb, float* __restrict__ dst)
{
    int row = blockIdx.x;
    int t = threadIdx.x;
    const float* in = src + (size_t)row * EE;
    float x0 = in[t], x1 = in[t + 256], x2 = in[t + 512];
    float mean = blk_sum(x0 + x1 + x2) * (1.f / EE);
    float d0 = x0 - mean, d1 = x1 - mean, d2 = x2 - mean;
    float var = blk_sum(d0 * d0 + d1 * d1 + d2 * d2) * (1.f / EE);
    float rs = rsqrtf(var + EPSV);
    float* o = dst + (size_t)row * EE;
    o[t]       = d0 * rs * g[t]       + bb[t];
    o[t + 256] = d1 * rs * g[t + 256] + bb[t + 256];
    o[t + 512] = d2 * rs * g[t + 512] + bb[t + 512];
}

// ---------------- LN post (cls token only) ----------------
__global__ void lnpost_kernel(const float* __restrict__ src, const float* __restrict__ g,
                              const float* __restrict__ bb, float* __restrict__ dst)
{
    int b = blockIdx.x;
    int t = threadIdx.x;
    const float* in = src + (size_t)(b * SS) * EE;   // s = 0
    float x0 = in[t], x1 = in[t + 256], x2 = in[t + 512];
    float mean = blk_sum(x0 + x1 + x2) * (1.f / EE);
    float d0 = x0 - mean, d1 = x1 - mean, d2 = x2 - mean;
    float var = blk_sum(d0 * d0 + d1 * d1 + d2 * d2) * (1.f / EE);
    float rs = rsqrtf(var + EPSV);
    float* o = dst + (size_t)b * EE;
    o[t]       = d0 * rs * g[t]       + bb[t];
    o[t + 256] = d1 * rs * g[t + 256] + bb[t + 256];
    o[t + 512] = d2 * rs * g[t + 512] + bb[t + 512];
}

// ---------------- fused attention (one block per (b,h)) ----------------
#define SM_ATTN_FLOATS (64 * KPAD + SS * 64 + 8 * KPAD + 8 * 64 + 16)
__global__ void attn_kernel(const float* __restrict__ qkv,
                            const float* __restrict__ coeff,
                            float* __restrict__ outp)
{
    extern __shared__ float sm[];
    float* Ks = sm;
    float* Vs = Ks + 64 * KPAD;
    float* Ar = Vs + SS * 64;
    float* Qs = Ar + 8 * KPAD;
    float* Co = Qs + 8 * 64;

    const int bh = blockIdx.x;
    const int b = bh / NH, h = bh % NH;
    const int tid = threadIdx.x;
    const int w = tid >> 5, lane = tid & 31;
    const float* base = qkv + (size_t)b * SS * (3 * EE);

    for (int idx = tid; idx < SS * 64; idx += 256) {
        int s = idx >> 6, d = idx & 63;
        const float* row = base + (size_t)s * (3 * EE) + h * HD;
        Ks[d * KPAD + s] = row[EE + d];
        Vs[idx]          = row[2 * EE + d];
    }
    if (tid < NPR) Co[tid] = coeff[tid];
    __syncthreads();

    for (int q = w; q < SS; q += 8) {
        const float* qrow = base + (size_t)q * (3 * EE) + h * HD;
        Qs[w * 64 + lane]      = qrow[lane];
        Qs[w * 64 + lane + 32] = qrow[lane + 32];
        __syncwarp();

        float sc[7];
#pragma unroll
        for (int i = 0; i < 7; i++) sc[i] = 0.f;
#pragma unroll 8
        for (int d = 0; d < 64; d++) {
            float qd = Qs[w * 64 + d];
#pragma unroll
            for (int i = 0; i < 7; i++)
                sc[i] += qd * Ks[d * KPAD + lane + 32 * i];
        }

        float m = -INFINITY;
#pragma unroll
        for (int i = 0; i < 7; i++) {
            int k = lane + 32 * i;
            if (k < SS) {
                float v = sc[i] * SCALEV;
                if (k >= NP) v *= Co[k - NP];
                sc[i] = v;
                m = fmaxf(m, v);
            } else sc[i] = -INFINITY;
        }
#pragma unroll
        for (int o = 16; o; o >>= 1) m = fmaxf(m, __shfl_xor_sync(0xffffffffu, m, o));

        float ssum = 0.f;
#pragma unroll
        for (int i = 0; i < 7; i++) {
            int k = lane + 32 * i;
            float p = __expf(sc[i] - m);
            if (k < SS) { ssum += p; Ar[w * KPAD + k] = p; }
        }
#pragma unroll
        for (int o = 16; o; o >>= 1) ssum += __shfl_xor_sync(0xffffffffu, ssum, o);
        __syncwarp();

        float o1 = 0.f, o2 = 0.f;
        for (int k = 0; k < SS; k++) {
            float a = Ar[w * KPAD + k];
            o1 += a * Vs[k * 64 + lane];
            o2 += a * Vs[k * 64 + lane + 32];
        }
        float inv = 1.f / ssum;
        float* orow = outp + (size_t)(b * SS + q) * EE + h * HD;
        orow[lane]      = o1 * inv;
        orow[lane + 32] = o2 * inv;
        __syncwarp();
    }
}

// ---------------- host launch ----------------
extern "C" void kernel_launch(void* const* d_in, const int* in_sizes, int n_in,
                              void* d_out, int out_size)
{
    const float* x        = (const float*)d_in[0];
    const float* coeff    = (const float*)d_in[1];
    const float* patch_w  = (const float*)d_in[2];
    const float* patch_b  = (const float*)d_in[3];
    const float* cls      = (const float*)d_in[4];
    const float* pos      = (const float*)d_in[5];
    const float* lnpre_g  = (const float*)d_in[6];
    const float* lnpre_b  = (const float*)d_in[7];
    const float* prompts  = (const float*)d_in[8];
    const float* ln1_g    = (const float*)d_in[9];
    const float* ln1_b    = (const float*)d_in[10];
    const float* qkv_w    = (const float*)d_in[11];
    const float* qkv_b    = (const float*)d_in[12];
    const float* proj_w   = (const float*)d_in[13];
    const float* proj_b   = (const float*)d_in[14];
    const float* ln2_g    = (const float*)d_in[15];
    const float* ln2_b    = (const float*)d_in[16];
    const float* fc1_w    = (const float*)d_in[17];
    const float* fc1_b    = (const float*)d_in[18];
    const float* fc2_w    = (const float*)d_in[19];
    const float* fc2_b    = (const float*)d_in[20];
    const float* lnpost_g = (const float*)d_in[21];
    const float* lnpost_b = (const float*)d_in[22];
    float* out = (float*)d_out;

    float *p_h, *p_hh, *p_qkv, *p_o, *p_ff;
    cudaGetSymbolAddress((void**)&p_h,  g_h);
    cudaGetSymbolAddress((void**)&p_hh, g_hh);
    cudaGetSymbolAddress((void**)&p_qkv, g_qkv);
    cudaGetSymbolAddress((void**)&p_o,  g_o);
    cudaGetSymbolAddress((void**)&p_ff, g_ff);

    const int smAttn = SM_ATTN_FLOATS * (int)sizeof(float);
    cudaFuncSetAttribute(attn_kernel, cudaFuncAttributeMaxDynamicSharedMemorySize, smAttn);

    // patch embedding: im2col -> GEMM -> compact conv output in p_o
    im2col_kernel<<<(MCONV * EE + 255) / 256, 256>>>(x, p_ff);
    tgemm_kernel<<<dim3(EE / 128, (MCONV + 127) / 128), 256>>>(
        p_ff, patch_w, patch_b, p_o, MCONV, EE, EE, 0);

    // cls + pos + ln_pre -> g_h (197 tokens per batch; prompt slots set per-layer)
    lnpre_kernel<<<BB * NP, 256>>>(p_o, cls, pos, lnpre_g, lnpre_b, p_h);

    const int mt = (BS + 127) / 128;   // 54
    for (int l = 0; l < NL; l++) {
        ln1_kernel<<<BS, 256>>>(p_h, prompts + (size_t)l * NPR * EE,
                                ln1_g + l * EE, ln1_b + l * EE, p_h, p_hh);
        tgemm_kernel<<<dim3(3 * EE / 128, mt), 256>>>(
            p_hh, qkv_w + (size_t)l * 3 * EE * EE, qkv_b + (size_t)l * 3 * EE,
            p_qkv, BS, 3 * EE, EE, 0);
        attn_kernel<<<BB * NH, 256, smAttn>>>(p_qkv, coeff + (size_t)l * NPR, p_o);
        tgemm_kernel<<<dim3(EE / 128, mt), 256>>>(
            p_o, proj_w + (size_t)l * EE * EE, proj_b + (size_t)l * EE,
            p_h, BS, EE, EE, 2);
        ln_kernel<<<BS, 256>>>(p_h, ln2_g + l * EE, ln2_b + l * EE, p_hh);
        tgemm_kernel<<<dim3(FFD / 128, mt), 256>>>(
            p_hh, fc1_w + (size_t)l * FFD * EE, fc1_b + (size_t)l * FFD,
            p_ff, BS, FFD, EE, 1);
        tgemm_kernel<<<dim3(EE / 128, mt), 256>>>(
            p_ff, fc2_w + (size_t)l * EE * FFD, fc2_b + (size_t)l * EE,
            p_h, BS, EE, FFD, 2);
    }

    lnpost_kernel<<<BB, 256>>>(p_h, lnpost_g, lnpost_b, out);
}

// round 5
// speedup vs baseline: 2.6958x; 1.1254x over previous
#include <cuda_runtime.h>
#include <math.h>
#include <stdint.h>

// ---------------- geometry ----------------
#define BB     32
#define CCH    3
#define IMG    224
#define PTCH   16
#define EE     768
#define NH     12
#define NL     12
#define NPR    16
#define NP     197
#define SS     213
#define HD     64
#define FFD    3072
#define EPSV   1e-6f
#define SCALEV 0.125f

#define BS      (BB * SS)          // 6816
#define NPATCH  196
#define MCONV   (BB * NPATCH)      // 6272

// ---------------- scratch (device globals: allowed) ----------------
__device__ float g_h  [(size_t)BS * EE];
__device__ float g_hh [(size_t)BS * EE];
__device__ float g_qkv[(size_t)BS * 3 * EE];
__device__ float g_o  [(size_t)BS * EE];
__device__ float g_ff [(size_t)BS * FFD];
// tf32-rounded weight copies
__device__ float g_wq [(size_t)NL * 3 * EE * EE];
__device__ float g_wp [(size_t)NL * EE * EE];
__device__ float g_w1 [(size_t)NL * FFD * EE];
__device__ float g_w2 [(size_t)NL * EE * FFD];
__device__ float g_wc [(size_t)EE * EE];

// ---------------- helpers ----------------
__device__ __forceinline__ float blk_sum(float v) {
    __shared__ float red[8];
    __shared__ float tot;
    int lane = threadIdx.x & 31, w = threadIdx.x >> 5;
#pragma unroll
    for (int o = 16; o; o >>= 1) v += __shfl_xor_sync(0xffffffffu, v, o);
    if (lane == 0) red[w] = v;
    __syncthreads();
    if (w == 0) {
        float t = (lane < 8) ? red[lane] : 0.f;
#pragma unroll
        for (int o = 4; o; o >>= 1) t += __shfl_xor_sync(0xffffffffu, t, o);
        if (lane == 0) tot = t;
    }
    __syncthreads();
    return tot;
}

__device__ __forceinline__ float tf32r(float f) {
    uint32_t u;
    asm("cvt.rna.tf32.f32 %0, %1;" : "=r"(u) : "f"(f));
    return __uint_as_float(u);
}

__device__ __forceinline__ void cpa16(void* dst, const void* src, int srcBytes) {
    uint32_t d = (uint32_t)__cvta_generic_to_shared(dst);
    asm volatile("cp.async.cg.shared.global [%0], [%1], 16, %2;"
                 :: "r"(d), "l"(src), "r"(srcBytes));
}

// ---------------- weight tf32 pre-round ----------------
__global__ void round_kernel(const float* __restrict__ src, float* __restrict__ dst, int n4) {
    int i = blockIdx.x * 256 + threadIdx.x;
    if (i >= n4) return;
    float4 v = ((const float4*)src)[i];
    v.x = tf32r(v.x); v.y = tf32r(v.y); v.z = tf32r(v.z); v.w = tf32r(v.w);
    ((float4*)dst)[i] = v;
}

// ---------------- im2col (tf32-rounded: feeds GEMM A) ----------------
__global__ void im2col_kernel(const float* __restrict__ x, float* __restrict__ out) {
    int idx = blockIdx.x * 256 + threadIdx.x;
    if (idx >= MCONV * EE) return;
    int m = idx / EE;
    int k = idx % EE;
    int b = m / NPATCH, p = m % NPATCH;
    int c = k >> 8, rem = k & 255, i = rem >> 4, j = rem & 15;
    int py = p / 14, px = p % 14;
    out[idx] = tf32r(x[(((size_t)b * CCH + c) * IMG + (py * PTCH + i)) * IMG + (px * PTCH + j)]);
}

// ---------------- TF32 tensor GEMM, cp.async 2-stage ----------------
// C[M,N] = A[M,K] * W[N,K]^T + bias ; inputs pre-rounded to tf32
// epi: 0 bias, 1 bias+GELU (output tf32-rounded), 2 bias+residual
#define SMPAD 36
#define TGEMM_SMEM (2 * 2 * 128 * SMPAD * 4)
__global__ __launch_bounds__(256)
void tgemm_kernel(const float* __restrict__ A, const float* __restrict__ Bw,
                  const float* __restrict__ bias, float* __restrict__ C,
                  int M, int N, int K, int epi)
{
    extern __shared__ float smg[];
    float* As = smg;                      // [2][128][SMPAD]
    float* Bs = smg + 2 * 128 * SMPAD;    // [2][128][SMPAD]

    const int tid  = threadIdx.x;
    const int warp = tid >> 5, lane = tid & 31;
    const int wm = warp >> 2;
    const int wn = warp & 3;
    const int r  = lane >> 2;
    const int cg = lane & 3;
    const int row0 = blockIdx.y * 128;
    const int col0 = blockIdx.x * 128;

    float acc[4][4][4];
#pragma unroll
    for (int mi = 0; mi < 4; mi++)
#pragma unroll
        for (int ni = 0; ni < 4; ni++)
#pragma unroll
            for (int e = 0; e < 4; e++) acc[mi][ni][e] = 0.f;

    const int lrow = tid >> 1;
    const int lk   = (tid & 1) * 16;
    const int abytes = ((row0 + lrow) < M) ? 16 : 0;
    const float* Aptr = A  + (size_t)(row0 + lrow) * K + lk;
    const float* Bptr = Bw + (size_t)(col0 + lrow) * K + lk;
    float* Asr = As + lrow * SMPAD + lk;
    float* Bsr = Bs + lrow * SMPAD + lk;

    // prefetch stage 0
#pragma unroll
    for (int i = 0; i < 4; i++) {
        cpa16(Asr + 4 * i, Aptr + 4 * i, abytes);
        cpa16(Bsr + 4 * i, Bptr + 4 * i, 16);
    }
    asm volatile("cp.async.commit_group;");

    int buf = 0;
    for (int k0 = 0; k0 < K; k0 += 32) {
        if (k0 + 32 < K) {
            int nb = (buf ^ 1) * 128 * SMPAD;
#pragma unroll
            for (int i = 0; i < 4; i++) {
                cpa16(Asr + nb + 4 * i, Aptr + k0 + 32 + 4 * i, abytes);
                cpa16(Bsr + nb + 4 * i, Bptr + k0 + 32 + 4 * i, 16);
            }
            asm volatile("cp.async.commit_group;");
            asm volatile("cp.async.wait_group 1;");
        } else {
            asm volatile("cp.async.wait_group 0;");
        }
        __syncthreads();

        const float* Ab = As + buf * 128 * SMPAD;
        const float* Bb = Bs + buf * 128 * SMPAD;
#pragma unroll
        for (int kk = 0; kk < 32; kk += 8) {
            uint32_t af[4][4], bf[4][2];
#pragma unroll
            for (int mi = 0; mi < 4; mi++) {
                int mr = wm * 64 + mi * 16;
                af[mi][0] = __float_as_uint(Ab[(mr + r    ) * SMPAD + kk + cg    ]);
                af[mi][1] = __float_as_uint(Ab[(mr + r + 8) * SMPAD + kk + cg    ]);
                af[mi][2] = __float_as_uint(Ab[(mr + r    ) * SMPAD + kk + cg + 4]);
                af[mi][3] = __float_as_uint(Ab[(mr + r + 8) * SMPAD + kk + cg + 4]);
            }
#pragma unroll
            for (int ni = 0; ni < 4; ni++) {
                int nc = wn * 32 + ni * 8;
                bf[ni][0] = __float_as_uint(Bb[(nc + r) * SMPAD + kk + cg    ]);
                bf[ni][1] = __float_as_uint(Bb[(nc + r) * SMPAD + kk + cg + 4]);
            }
#pragma unroll
            for (int mi = 0; mi < 4; mi++)
#pragma unroll
                for (int ni = 0; ni < 4; ni++) {
                    asm volatile(
                        "mma.sync.aligned.m16n8k8.row.col.f32.tf32.tf32.f32 "
                        "{%0,%1,%2,%3}, {%4,%5,%6,%7}, {%8,%9}, {%0,%1,%2,%3};"
                        : "+f"(acc[mi][ni][0]), "+f"(acc[mi][ni][1]),
                          "+f"(acc[mi][ni][2]), "+f"(acc[mi][ni][3])
                        : "r"(af[mi][0]), "r"(af[mi][1]), "r"(af[mi][2]), "r"(af[mi][3]),
                          "r"(bf[ni][0]), "r"(bf[ni][1]));
                }
        }
        __syncthreads();
        buf ^= 1;
    }

#pragma unroll
    for (int mi = 0; mi < 4; mi++) {
        int mr0 = row0 + wm * 64 + mi * 16 + r;
#pragma unroll
        for (int ni = 0; ni < 4; ni++) {
            int nc = col0 + wn * 32 + ni * 8 + 2 * cg;
            float b0 = bias[nc], b1 = bias[nc + 1];
#pragma unroll
            for (int half = 0; half < 2; half++) {
                int rr = mr0 + half * 8;
                if (rr >= M) continue;
                float v0 = acc[mi][ni][half * 2 + 0] + b0;
                float v1 = acc[mi][ni][half * 2 + 1] + b1;
                if (epi == 1) {
                    v0 = tf32r(0.5f * v0 * (1.f + erff(v0 * 0.70710678118654752f)));
                    v1 = tf32r(0.5f * v1 * (1.f + erff(v1 * 0.70710678118654752f)));
                }
                size_t idx = (size_t)rr * N + nc;
                if (epi == 2) { v0 += C[idx]; v1 += C[idx + 1]; }
                C[idx] = v0; C[idx + 1] = v1;
            }
        }
    }
}

// ---------------- LN pre (cls/pos assembly; residual stream: no rounding) ----
__global__ void lnpre_kernel(const float* __restrict__ conv, const float* __restrict__ cls,
                             const float* __restrict__ pos, const float* __restrict__ g,
                             const float* __restrict__ bb, float* __restrict__ dst)
{
    int row = blockIdx.x;
    int b = row / NP, s = row % NP;
    int t = threadIdx.x;
    const float* base = (s == 0) ? cls : conv + (size_t)(b * NPATCH + s - 1) * EE;
    const float* pr = pos + (size_t)s * EE;
    float x0 = base[t] + pr[t];
    float x1 = base[t + 256] + pr[t + 256];
    float x2 = base[t + 512] + pr[t + 512];
    float mean = blk_sum(x0 + x1 + x2) * (1.f / EE);
    float d0 = x0 - mean, d1 = x1 - mean, d2 = x2 - mean;
    float var = blk_sum(d0 * d0 + d1 * d1 + d2 * d2) * (1.f / EE);
    float rs = rsqrtf(var + EPSV);
    float* o = dst + (size_t)(b * SS + s) * EE;
    o[t]       = d0 * rs * g[t]       + bb[t];
    o[t + 256] = d1 * rs * g[t + 256] + bb[t + 256];
    o[t + 512] = d2 * rs * g[t + 512] + bb[t + 512];
}

// ---------------- LN1 (prompt substitution; out tf32-rounded -> qkv GEMM) ----
__global__ void ln1_kernel(const float* __restrict__ src, const float* __restrict__ prompt,
                           const float* __restrict__ g, const float* __restrict__ bb,
                           float* __restrict__ hwr, float* __restrict__ dst)
{
    int row = blockIdx.x;
    int s = row % SS;
    int t = threadIdx.x;
    const float* in = (s < NP) ? src + (size_t)row * EE
                               : prompt + (size_t)(s - NP) * EE;
    float x0 = in[t], x1 = in[t + 256], x2 = in[t + 512];
    if (s >= NP) {
        float* hw = hwr + (size_t)row * EE;
        hw[t] = x0; hw[t + 256] = x1; hw[t + 512] = x2;
    }
    float mean = blk_sum(x0 + x1 + x2) * (1.f / EE);
    float d0 = x0 - mean, d1 = x1 - mean, d2 = x2 - mean;
    float var = blk_sum(d0 * d0 + d1 * d1 + d2 * d2) * (1.f / EE);
    float rs = rsqrtf(var + EPSV);
    float* o = dst + (size_t)row * EE;
    o[t]       = tf32r(d0 * rs * g[t]       + bb[t]);
    o[t + 256] = tf32r(d1 * rs * g[t + 256] + bb[t + 256]);
    o[t + 512] = tf32r(d2 * rs * g[t + 512] + bb[t + 512]);
}

// ---------------- LN2 (out tf32-rounded -> fc1 GEMM) ----------------
__global__ void ln_kernel(const float* __restrict__ src, const float* __restrict__ g,
                          const float* __restrict__ bb, float* __restrict__ dst)
{
    int row = blockIdx.x;
    int t = threadIdx.x;
    const float* in = src + (size_t)row * EE;
    float x0 = in[t], x1 = in[t + 256], x2 = in[t + 512];
    float mean = blk_sum(x0 + x1 + x2) * (1.f / EE);
    float d0 = x0 - mean, d1 = x1 - mean, d2 = x2 - mean;
    float var = blk_sum(d0 * d0 + d1 * d1 + d2 * d2) * (1.f / EE);
    float rs = rsqrtf(var + EPSV);
    float* o = dst + (size_t)row * EE;
    o[t]       = tf32r(d0 * rs * g[t]       + bb[t]);
    o[t + 256] = tf32r(d1 * rs * g[t + 256] + bb[t + 256]);
    o[t + 512] = tf32r(d2 * rs * g[t + 512] + bb[t + 512]);
}

// ---------------- LN post (cls only; final output: no rounding) -------------
__global__ void lnpost_kernel(const float* __restrict__ src, const float* __restrict__ g,
                              const float* __restrict__ bb, float* __restrict__ dst)
{
    int b = blockIdx.x;
    int t = threadIdx.x;
    const float* in = src + (size_t)(b * SS) * EE;
    float x0 = in[t], x1 = in[t + 256], x2 = in[t + 512];
    float mean = blk_sum(x0 + x1 + x2) * (1.f / EE);
    float d0 = x0 - mean, d1 = x1 - mean, d2 = x2 - mean;
    float var = blk_sum(d0 * d0 + d1 * d1 + d2 * d2) * (1.f / EE);
    float rs = rsqrtf(var + EPSV);
    float* o = dst + (size_t)b * EE;
    o[t]       = d0 * rs * g[t]       + bb[t];
    o[t + 256] = d1 * rs * g[t + 256] + bb[t + 256];
    o[t + 512] = d2 * rs * g[t + 512] + bb[t + 512];
}

// ---------------- fused attention: 4 queries/warp, float4 smem paths --------
#define KSRP 68
#define VSTP 220
#define ARP  216
#define QB   4
#define QG   ((SS + QB - 1) / QB)   // 54
#define SM_ATTN_FLOATS (224 * KSRP + 64 * VSTP + 8 * QB * ARP + 8 * QB * 64 + 16)
__global__ void attn_kernel(const float* __restrict__ qkv,
                            const float* __restrict__ coeff,
                            float* __restrict__ outp)
{
    extern __shared__ float sm[];
    float* Ksr = sm;                          // [224][KSRP] row-major K
    float* Vst = Ksr + 224 * KSRP;            // [64][VSTP]  V transposed
    float* Ar  = Vst + 64 * VSTP;             // [8][QB][ARP]
    float* Qs  = Ar + 8 * QB * ARP;           // [8][QB][64]
    float* Co  = Qs + 8 * QB * 64;            // [16]

    const int bh = blockIdx.x;
    const int b = bh / NH, h = bh % NH;
    const int tid = threadIdx.x;
    const int w = tid >> 5, lane = tid & 31;
    const float* base = qkv + (size_t)b * SS * (3 * EE);

    for (int idx = tid; idx < SS * 64; idx += 256) {
        int s = idx >> 6, d = idx & 63;
        const float* row = base + (size_t)s * (3 * EE) + h * HD;
        Ksr[s * KSRP + d]  = row[EE + d];
        Vst[d * VSTP + s]  = row[2 * EE + d];
    }
    // zero pads: K rows 213..223, V cols 213..216
    for (int idx = tid; idx < 11 * 64; idx += 256) {
        int s = 213 + (idx >> 6), d = idx & 63;
        Ksr[s * KSRP + d] = 0.f;
    }
    { int d = tid >> 2, s = 213 + (tid & 3); Vst[d * VSTP + s] = 0.f; }
    if (tid < NPR) Co[tid] = coeff[tid];
    __syncthreads();

    for (int g = w; g < QG; g += 8) {
        const int q0 = g * QB;
        float* Qw = Qs + (w * QB) * 64;
        float* Aw = Ar + (w * QB) * ARP;
#pragma unroll
        for (int qq = 0; qq < QB; qq++) {
            int q = q0 + qq; if (q >= SS) q = SS - 1;
            const float* qrow = base + (size_t)q * (3 * EE) + h * HD;
            Qw[qq * 64 + lane]      = qrow[lane];
            Qw[qq * 64 + lane + 32] = qrow[lane + 32];
        }
        __syncwarp();

        float sc[QB][7];
#pragma unroll
        for (int qq = 0; qq < QB; qq++)
#pragma unroll
            for (int i = 0; i < 7; i++) sc[qq][i] = 0.f;

#pragma unroll 4
        for (int d = 0; d < 64; d += 4) {
            float4 q4[QB];
#pragma unroll
            for (int qq = 0; qq < QB; qq++)
                q4[qq] = *(const float4*)&Qw[qq * 64 + d];
#pragma unroll
            for (int i = 0; i < 7; i++) {
                int k = lane + 32 * i;
                float4 kv = *(const float4*)&Ksr[k * KSRP + d];
#pragma unroll
                for (int qq = 0; qq < QB; qq++)
                    sc[qq][i] += q4[qq].x * kv.x + q4[qq].y * kv.y
                               + q4[qq].z * kv.z + q4[qq].w * kv.w;
            }
        }

        float inv[QB];
#pragma unroll
        for (int qq = 0; qq < QB; qq++) {
            float m = -INFINITY;
#pragma unroll
            for (int i = 0; i < 7; i++) {
                int k = lane + 32 * i;
                if (k < SS) {
                    float v = sc[qq][i] * SCALEV;
                    if (k >= NP) v *= Co[k - NP];
                    sc[qq][i] = v;
                    m = fmaxf(m, v);
                } else sc[qq][i] = -INFINITY;
            }
#pragma unroll
            for (int o = 16; o; o >>= 1) m = fmaxf(m, __shfl_xor_sync(0xffffffffu, m, o));
            float ssum = 0.f;
#pragma unroll
            for (int i = 0; i < 7; i++) {
                int k = lane + 32 * i;
                float p = __expf(sc[qq][i] - m);
                if (k < SS) { ssum += p; Aw[qq * ARP + k] = p; }
                else if (k < ARP) Aw[qq * ARP + k] = 0.f;
            }
#pragma unroll
            for (int o = 16; o; o >>= 1) ssum += __shfl_xor_sync(0xffffffffu, ssum, o);
            inv[qq] = 1.f / ssum;
        }
        __syncwarp();

        float o1[QB], o2[QB];
#pragma unroll
        for (int qq = 0; qq < QB; qq++) { o1[qq] = 0.f; o2[qq] = 0.f; }
#pragma unroll 2
        for (int k0 = 0; k0 < ARP; k0 += 4) {
            float4 v1 = *(const float4*)&Vst[lane * VSTP + k0];
            float4 v2 = *(const float4*)&Vst[(lane + 32) * VSTP + k0];
#pragma unroll
            for (int qq = 0; qq < QB; qq++) {
                float4 a4 = *(const float4*)&Aw[qq * ARP + k0];
                o1[qq] += a4.x * v1.x + a4.y * v1.y + a4.z * v1.z + a4.w * v1.w;
                o2[qq] += a4.x * v2.x + a4.y * v2.y + a4.z * v2.z + a4.w * v2.w;
            }
        }
#pragma unroll
        for (int qq = 0; qq < QB; qq++) {
            int q = q0 + qq;
            if (q < SS) {
                float* orow = outp + (size_t)(b * SS + q) * EE + h * HD;
                orow[lane]      = tf32r(o1[qq] * inv[qq]);
                orow[lane + 32] = tf32r(o2[qq] * inv[qq]);
            }
        }
        __syncwarp();
    }
}

// ---------------- host launch ----------------
extern "C" void kernel_launch(void* const* d_in, const int* in_sizes, int n_in,
                              void* d_out, int out_size)
{
    const float* x        = (const float*)d_in[0];
    const float* coeff    = (const float*)d_in[1];
    const float* patch_w  = (const float*)d_in[2];
    const float* patch_b  = (const float*)d_in[3];
    const float* cls      = (const float*)d_in[4];
    const float* pos      = (const float*)d_in[5];
    const float* lnpre_g  = (const float*)d_in[6];
    const float* lnpre_b  = (const float*)d_in[7];
    const float* prompts  = (const float*)d_in[8];
    const float* ln1_g    = (const float*)d_in[9];
    const float* ln1_b    = (const float*)d_in[10];
    const float* qkv_w    = (const float*)d_in[11];
    const float* qkv_b    = (const float*)d_in[12];
    const float* proj_w   = (const float*)d_in[13];
    const float* proj_b   = (const float*)d_in[14];
    const float* ln2_g    = (const float*)d_in[15];
    const float* ln2_b    = (const float*)d_in[16];
    const float* fc1_w    = (const float*)d_in[17];
    const float* fc1_b    = (const float*)d_in[18];
    const float* fc2_w    = (const float*)d_in[19];
    const float* fc2_b    = (const float*)d_in[20];
    const float* lnpost_g = (const float*)d_in[21];
    const float* lnpost_b = (const float*)d_in[22];
    float* out = (float*)d_out;

    float *p_h, *p_hh, *p_qkv, *p_o, *p_ff, *p_wq, *p_wp, *p_w1, *p_w2, *p_wc;
    cudaGetSymbolAddress((void**)&p_h,  g_h);
    cudaGetSymbolAddress((void**)&p_hh, g_hh);
    cudaGetSymbolAddress((void**)&p_qkv, g_qkv);
    cudaGetSymbolAddress((void**)&p_o,  g_o);
    cudaGetSymbolAddress((void**)&p_ff, g_ff);
    cudaGetSymbolAddress((void**)&p_wq, g_wq);
    cudaGetSymbolAddress((void**)&p_wp, g_wp);
    cudaGetSymbolAddress((void**)&p_w1, g_w1);
    cudaGetSymbolAddress((void**)&p_w2, g_w2);
    cudaGetSymbolAddress((void**)&p_wc, g_wc);

    const int smAttn = SM_ATTN_FLOATS * (int)sizeof(float);
    cudaFuncSetAttribute(attn_kernel, cudaFuncAttributeMaxDynamicSharedMemorySize, smAttn);
    cudaFuncSetAttribute(tgemm_kernel, cudaFuncAttributeMaxDynamicSharedMemorySize, TGEMM_SMEM);

    // pre-round all weights to tf32 (feeds cp.async path with exact RNA numerics)
    {
        int n;
        n = NL * 3 * EE * EE / 4; round_kernel<<<(n + 255) / 256, 256>>>(qkv_w,  p_wq, n);
        n = NL * EE * EE / 4;     round_kernel<<<(n + 255) / 256, 256>>>(proj_w, p_wp, n);
        n = NL * FFD * EE / 4;    round_kernel<<<(n + 255) / 256, 256>>>(fc1_w,  p_w1, n);
        n = NL * EE * FFD / 4;    round_kernel<<<(n + 255) / 256, 256>>>(fc2_w,  p_w2, n);
        n = EE * EE / 4;          round_kernel<<<(n + 255) / 256, 256>>>(patch_w, p_wc, n);
    }

    // patch embedding
    im2col_kernel<<<(MCONV * EE + 255) / 256, 256>>>(x, p_ff);
    tgemm_kernel<<<dim3(EE / 128, (MCONV + 127) / 128), 256, TGEMM_SMEM>>>(
        p_ff, p_wc, patch_b, p_o, MCONV, EE, EE, 0);

    lnpre_kernel<<<BB * NP, 256>>>(p_o, cls, pos, lnpre_g, lnpre_b, p_h);

    const int mt = (BS + 127) / 128;   // 54
    for (int l = 0; l < NL; l++) {
        ln1_kernel<<<BS, 256>>>(p_h, prompts + (size_t)l * NPR * EE,
                                ln1_g + l * EE, ln1_b + l * EE, p_h, p_hh);
        tgemm_kernel<<<dim3(3 * EE / 128, mt), 256, TGEMM_SMEM>>>(
            p_hh, p_wq + (size_t)l * 3 * EE * EE, qkv_b + (size_t)l * 3 * EE,
            p_qkv, BS, 3 * EE, EE, 0);
        attn_kernel<<<BB * NH, 256, smAttn>>>(p_qkv, coeff + (size_t)l * NPR, p_o);
        tgemm_kernel<<<dim3(EE / 128, mt), 256, TGEMM_SMEM>>>(
            p_o, p_wp + (size_t)l * EE * EE, proj_b + (size_t)l * EE,
            p_h, BS, EE, EE, 2);
        ln_kernel<<<BS, 256>>>(p_h, ln2_g + l * EE, ln2_b + l * EE, p_hh);
        tgemm_kernel<<<dim3(FFD / 128, mt), 256, TGEMM_SMEM>>>(
            p_hh, p_w1 + (size_t)l * FFD * EE, fc1_b + (size_t)l * FFD,
            p_ff, BS, FFD, EE, 1);
        tgemm_kernel<<<dim3(EE / 128, mt), 256, TGEMM_SMEM>>>(
            p_ff, p_w2 + (size_t)l * EE * FFD, fc2_b + (size_t)l * EE,
            p_h, BS, EE, FFD, 2);
    }

    lnpost_kernel<<<BB, 256>>>(p_h, lnpost_g, lnpost_b, out);
}

// round 9
// speedup vs baseline: 5.2692x; 1.9546x over previous
#include <cuda_runtime.h>
#include <cuda_fp16.h>
#include <math.h>
#include <stdint.h>

// ---------------- geometry ----------------
#define BB     32
#define CCH    3
#define IMG    224
#define PTCH   16
#define EE     768
#define NH     12
#define NL     12
#define NPR    16
#define NP     197
#define SS     213
#define HD     64
#define FFD    3072
#define EPSV   1e-6f
#define SCALEV 0.125f

#define BS      (BB * SS)          // 6816
#define NPATCH  196
#define MCONV   (BB * NPATCH)      // 6272

// ---------------- scratch (device globals: allowed) ----------------
__device__ float  g_h  [(size_t)BS * EE];          // fp32 residual stream
__device__ __half g_hh [(size_t)BS * EE];          // LN outputs (half)
__device__ float  g_qkv[(size_t)BS * 3 * EE];      // qkv (fp32, read by attention)
__device__ __half g_oh [(size_t)BS * EE];          // attention out (half)
__device__ __half g_ffh[(size_t)BS * FFD];         // fc1 out / im2col (half)
__device__ float  g_o  [(size_t)BS * EE];          // conv out (fp32)
// fp16 weight copies
__device__ __half g_wq [(size_t)NL * 3 * EE * EE];
__device__ __half g_wp [(size_t)NL * EE * EE];
__device__ __half g_w1 [(size_t)NL * FFD * EE];
__device__ __half g_w2 [(size_t)NL * EE * FFD];
__device__ __half g_wc [(size_t)EE * EE];

// ---------------- helpers ----------------
__device__ __forceinline__ float blk_sum(float v) {
    __shared__ float red[8];
    __shared__ float tot;
    int lane = threadIdx.x & 31, w = threadIdx.x >> 5;
#pragma unroll
    for (int o = 16; o; o >>= 1) v += __shfl_xor_sync(0xffffffffu, v, o);
    if (lane == 0) red[w] = v;
    __syncthreads();
    if (w == 0) {
        float t = (lane < 8) ? red[lane] : 0.f;
#pragma unroll
        for (int o = 4; o; o >>= 1) t += __shfl_xor_sync(0xffffffffu, t, o);
        if (lane == 0) tot = t;
    }
    __syncthreads();
    return tot;
}

__device__ __forceinline__ void cpa16_s(uint32_t dst, const void* src, int srcBytes) {
    asm volatile("cp.async.cg.shared.global [%0], [%1], 16, %2;"
                 :: "r"(dst), "l"(src), "r"(srcBytes));
}

__device__ __forceinline__ uint32_t lds32(uint32_t a) {
    uint32_t v;
    asm volatile("ld.shared.b32 %0, [%1];" : "=r"(v) : "r"(a));
    return v;
}

// ---------------- weight fp16 convert ----------------
__global__ void cvt_kernel(const float* __restrict__ src, __half* __restrict__ dst, int n4) {
    int i = blockIdx.x * 256 + threadIdx.x;
    if (i >= n4) return;
    float4 v = ((const float4*)src)[i];
    __half2 h0 = __floats2half2_rn(v.x, v.y);
    __half2 h1 = __floats2half2_rn(v.z, v.w);
    ((__half2*)dst)[2 * i]     = h0;
    ((__half2*)dst)[2 * i + 1] = h1;
}

// ---------------- im2col (half out: feeds GEMM A) ----------------
__global__ void im2col_kernel(const float* __restrict__ x, __half* __restrict__ out) {
    int idx = blockIdx.x * 256 + threadIdx.x;
    if (idx >= MCONV * EE) return;
    int m = idx / EE;
    int k = idx % EE;
    int b = m / NPATCH, p = m % NPATCH;
    int c = k >> 8, rem = k & 255, i = rem >> 4, j = rem & 15;
    int py = p / 14, px = p % 14;
    out[idx] = __float2half_rn(
        x[(((size_t)b * CCH + c) * IMG + (py * PTCH + i)) * IMG + (px * PTCH + j)]);
}

// ---------------- FP16 tensor GEMM (mma.sync m16n8k16), 3-stage cp.async ----
// C[M,N] = A[M,K] * W[N,K]^T + bias
// epi 0: fp32 out Cf ; epi 1: bias+GELU -> half out Ch ; epi 2: bias+residual -> Cf
#define KT        64                        // k-tile (halfs)
#define RSB       144                       // smem row stride bytes (128 data + 16 pad)
#define MAT_BYTES (128 * RSB)               // 18432
#define STG_BYTES (2 * MAT_BYTES)           // 36864 (A + B)
#define NSTAGE    3
#define TG_SMEM   (NSTAGE * STG_BYTES)      // 110592

__global__ __launch_bounds__(256)
void hgemm_kernel(const __half* __restrict__ A, const __half* __restrict__ Bw,
                  const float* __restrict__ bias, float* __restrict__ Cf,
                  __half* __restrict__ Ch, int M, int N, int K, int epi)
{
    extern __shared__ char smg[];
    const uint32_t smem_base = (uint32_t)__cvta_generic_to_shared(smg);
    const int tid  = threadIdx.x;
    const int warp = tid >> 5, lane = tid & 31;
    const int wm = warp >> 2;            // 0..1 (64 rows)
    const int wn = warp & 3;             // 0..3 (32 cols)
    const int r  = lane >> 2;            // 0..7
    const int cg = lane & 3;             // 0..3
    const int row0 = blockIdx.y * 128;
    const int col0 = blockIdx.x * 128;

    float acc[4][4][4];
#pragma unroll
    for (int mi = 0; mi < 4; mi++)
#pragma unroll
        for (int ni = 0; ni < 4; ni++)
#pragma unroll
            for (int e = 0; e < 4; e++) acc[mi][ni][e] = 0.f;

    const int frow   = tid >> 3;         // 0..31
    const int fcol16 = tid & 7;          // 0..7 (16B chunks per 128B row)
    const int nc = K / KT;

    // fill lambda-ish macro
#define FILL(sidx, kk0)                                                          \
    {                                                                            \
        uint32_t sA = smem_base + (sidx) * STG_BYTES;                            \
        uint32_t sB = sA + MAT_BYTES;                                            \
        _Pragma("unroll")                                                        \
        for (int c = 0; c < 4; c++) {                                            \
            int row = frow + c * 32;                                             \
            uint32_t doff = (uint32_t)row * RSB + fcol16 * 16;                   \
            cpa16_s(sA + doff, A + (size_t)(row0 + row) * K + (kk0) + fcol16 * 8,\
                    (row0 + row < M) ? 16 : 0);                                  \
            cpa16_s(sB + doff, Bw + (size_t)(col0 + row) * K + (kk0) + fcol16 * 8, 16);\
        }                                                                        \
        asm volatile("cp.async.commit_group;");                                  \
    }

    FILL(0, 0);
    if (nc > 1) FILL(1, KT);

    for (int i = 0; i < nc; i++) {
        if (i + 2 < nc) {
            FILL((i + 2) % NSTAGE, (i + 2) * KT);
            asm volatile("cp.async.wait_group 2;");
        } else if (i + 1 < nc) {
            asm volatile("cp.async.wait_group 1;");
        } else {
            asm volatile("cp.async.wait_group 0;");
        }
        __syncthreads();

        const uint32_t sA = smem_base + (i % NSTAGE) * STG_BYTES;
        const uint32_t sB = sA + MAT_BYTES;
#pragma unroll
        for (int kk = 0; kk < KT; kk += 16) {
            uint32_t af[4][4], bf[4][2];
#pragma unroll
            for (int mi = 0; mi < 4; mi++) {
                uint32_t base = sA + (uint32_t)(wm * 64 + mi * 16 + r) * RSB + (kk + 2 * cg) * 2;
                af[mi][0] = lds32(base);
                af[mi][1] = lds32(base + 8 * RSB);
                af[mi][2] = lds32(base + 16);
                af[mi][3] = lds32(base + 8 * RSB + 16);
            }
#pragma unroll
            for (int ni = 0; ni < 4; ni++) {
                uint32_t base = sB + (uint32_t)(wn * 32 + ni * 8 + r) * RSB + (kk + 2 * cg) * 2;
                bf[ni][0] = lds32(base);
                bf[ni][1] = lds32(base + 16);
            }
#pragma unroll
            for (int mi = 0; mi < 4; mi++)
#pragma unroll
                for (int ni = 0; ni < 4; ni++) {
                    asm volatile(
                        "mma.sync.aligned.m16n8k16.row.col.f32.f16.f16.f32 "
                        "{%0,%1,%2,%3}, {%4,%5,%6,%7}, {%8,%9}, {%0,%1,%2,%3};"
                        : "+f"(acc[mi][ni][0]), "+f"(acc[mi][ni][1]),
                          "+f"(acc[mi][ni][2]), "+f"(acc[mi][ni][3])
                        : "r"(af[mi][0]), "r"(af[mi][1]), "r"(af[mi][2]), "r"(af[mi][3]),
                          "r"(bf[ni][0]), "r"(bf[ni][1]));
                }
        }
        __syncthreads();
    }
#undef FILL

    // epilogue
#pragma unroll
    for (int mi = 0; mi < 4; mi++) {
        int mr0 = row0 + wm * 64 + mi * 16 + r;
#pragma unroll
        for (int ni = 0; ni < 4; ni++) {
            int nc2 = col0 + wn * 32 + ni * 8 + 2 * cg;
            float b0 = bias[nc2], b1 = bias[nc2 + 1];
#pragma unroll
            for (int half_ = 0; half_ < 2; half_++) {
                int rr = mr0 + half_ * 8;
                if (rr >= M) continue;
                float v0 = acc[mi][ni][half_ * 2 + 0] + b0;
                float v1 = acc[mi][ni][half_ * 2 + 1] + b1;
                size_t idx = (size_t)rr * N + nc2;
                if (epi == 1) {
                    v0 = 0.5f * v0 * (1.f + erff(v0 * 0.70710678118654752f));
                    v1 = 0.5f * v1 * (1.f + erff(v1 * 0.70710678118654752f));
                    Ch[idx]     = __float2half_rn(v0);
                    Ch[idx + 1] = __float2half_rn(v1);
                } else {
                    if (epi == 2) { v0 += Cf[idx]; v1 += Cf[idx + 1]; }
                    Cf[idx] = v0; Cf[idx + 1] = v1;
                }
            }
        }
    }
}

// ---------------- LN pre (cls/pos assembly; fp32 out) ----------------
__global__ void lnpre_kernel(const float* __restrict__ conv, const float* __restrict__ cls,
                             const float* __restrict__ pos, const float* __restrict__ g,
                             const float* __restrict__ bb, float* __restrict__ dst)
{
    int row = blockIdx.x;
    int b = row / NP, s = row % NP;
    int t = threadIdx.x;
    const float* base = (s == 0) ? cls : conv + (size_t)(b * NPATCH + s - 1) * EE;
    const float* pr = pos + (size_t)s * EE;
    float x0 = base[t] + pr[t];
    float x1 = base[t + 256] + pr[t + 256];
    float x2 = base[t + 512] + pr[t + 512];
    float mean = blk_sum(x0 + x1 + x2) * (1.f / EE);
    float d0 = x0 - mean, d1 = x1 - mean, d2 = x2 - mean;
    float var = blk_sum(d0 * d0 + d1 * d1 + d2 * d2) * (1.f / EE);
    float rs = rsqrtf(var + EPSV);
    float* o = dst + (size_t)(b * SS + s) * EE;
    o[t]       = d0 * rs * g[t]       + bb[t];
    o[t + 256] = d1 * rs * g[t + 256] + bb[t + 256];
    o[t + 512] = d2 * rs * g[t + 512] + bb[t + 512];
}

// ---------------- LN1 (prompt substitution; half out) ----------------
__global__ void ln1_kernel(const float* __restrict__ src, const float* __restrict__ prompt,
                           const float* __restrict__ g, const float* __restrict__ bb,
                           float* __restrict__ hwr, __half* __restrict__ dst)
{
    int row = blockIdx.x;
    int s = row % SS;
    int t = threadIdx.x;
    const float* in = (s < NP) ? src + (size_t)row * EE
                               : prompt + (size_t)(s - NP) * EE;
    float x0 = in[t], x1 = in[t + 256], x2 = in[t + 512];
    if (s >= NP) {
        float* hw = hwr + (size_t)row * EE;
        hw[t] = x0; hw[t + 256] = x1; hw[t + 512] = x2;
    }
    float mean = blk_sum(x0 + x1 + x2) * (1.f / EE);
    float d0 = x0 - mean, d1 = x1 - mean, d2 = x2 - mean;
    float var = blk_sum(d0 * d0 + d1 * d1 + d2 * d2) * (1.f / EE);
    float rs = rsqrtf(var + EPSV);
    __half* o = dst + (size_t)row * EE;
    o[t]       = __float2half_rn(d0 * rs * g[t]       + bb[t]);
    o[t + 256] = __float2half_rn(d1 * rs * g[t + 256] + bb[t + 256]);
    o[t + 512] = __float2half_rn(d2 * rs * g[t + 512] + bb[t + 512]);
}

// ---------------- LN2 (half out) ----------------
__global__ void ln_kernel(const float* __restrict__ src, const float* __restrict__ g,
                          const float* __restrict__ bb, __half* __restrict__ dst)
{
    int row = blockIdx.x;
    int t = threadIdx.x;
    const float* in = src + (size_t)row * EE;
    float x0 = in[t], x1 = in[t + 256], x2 = in[t + 512];
    float mean = blk_sum(x0 + x1 + x2) * (1.f / EE);
    float d0 = x0 - mean, d1 = x1 - mean, d2 = x2 - mean;
    float var = blk_sum(d0 * d0 + d1 * d1 + d2 * d2) * (1.f / EE);
    float rs = rsqrtf(var + EPSV);
    __half* o = dst + (size_t)row * EE;
    o[t]       = __float2half_rn(d0 * rs * g[t]       + bb[t]);
    o[t + 256] = __float2half_rn(d1 * rs * g[t + 256] + bb[t + 256]);
    o[t + 512] = __float2half_rn(d2 * rs * g[t + 512] + bb[t + 512]);
}

// ---------------- LN post (cls only; fp32 out) ----------------
__global__ void lnpost_kernel(const float* __restrict__ src, const float* __restrict__ g,
                              const float* __restrict__ bb, float* __restrict__ dst)
{
    int b = blockIdx.x;
    int t = threadIdx.x;
    const float* in = src + (size_t)(b * SS) * EE;
    float x0 = in[t], x1 = in[t + 256], x2 = in[t + 512];
    float mean = blk_sum(x0 + x1 + x2) * (1.f / EE);
    float d0 = x0 - mean, d1 = x1 - mean, d2 = x2 - mean;
    float var = blk_sum(d0 * d0 + d1 * d1 + d2 * d2) * (1.f / EE);
    float rs = rsqrtf(var + EPSV);
    float* o = dst + (size_t)b * EE;
    o[t]       = d0 * rs * g[t]       + bb[t];
    o[t + 256] = d1 * rs * g[t + 256] + bb[t + 256];
    o[t + 512] = d2 * rs * g[t + 512] + bb[t + 512];
}

// ---------------- fused attention: 4 queries/warp, float4 smem paths --------
#define KSRP 68
#define VSTP 220
#define ARP  216
#define QB   4
#define QG   ((SS + QB - 1) / QB)   // 54
#define SM_ATTN_FLOATS (224 * KSRP + 64 * VSTP + 8 * QB * ARP + 8 * QB * 64 + 16)
__global__ void attn_kernel(const float* __restrict__ qkv,
                            const float* __restrict__ coeff,
                            __half* __restrict__ outp)
{
    extern __shared__ float sm[];
    float* Ksr = sm;
    float* Vst = Ksr + 224 * KSRP;
    float* Ar  = Vst + 64 * VSTP;
    float* Qs  = Ar + 8 * QB * ARP;
    float* Co  = Qs + 8 * QB * 64;

    const int bh = blockIdx.x;
    const int b = bh / NH, h = bh % NH;
    const int tid = threadIdx.x;
    const int w = tid >> 5, lane = tid & 31;
    const float* base = qkv + (size_t)b * SS * (3 * EE);

    for (int idx = tid; idx < SS * 64; idx += 256) {
        int s = idx >> 6, d = idx & 63;
        const float* row = base + (size_t)s * (3 * EE) + h * HD;
        Ksr[s * KSRP + d]  = row[EE + d];
        Vst[d * VSTP + s]  = row[2 * EE + d];
    }
    for (int idx = tid; idx < 11 * 64; idx += 256) {
        int s = 213 + (idx >> 6), d = idx & 63;
        Ksr[s * KSRP + d] = 0.f;
    }
    { int d = tid >> 2, s = 213 + (tid & 3); Vst[d * VSTP + s] = 0.f; }
    if (tid < NPR) Co[tid] = coeff[tid];
    __syncthreads();

    for (int g = w; g < QG; g += 8) {
        const int q0 = g * QB;
        float* Qw = Qs + (w * QB) * 64;
        float* Aw = Ar + (w * QB) * ARP;
#pragma unroll
        for (int qq = 0; qq < QB; qq++) {
            int q = q0 + qq; if (q >= SS) q = SS - 1;
            const float* qrow = base + (size_t)q * (3 * EE) + h * HD;
            Qw[qq * 64 + lane]      = qrow[lane];
            Qw[qq * 64 + lane + 32] = qrow[lane + 32];
        }
        __syncwarp();

        float sc[QB][7];
#pragma unroll
        for (int qq = 0; qq < QB; qq++)
#pragma unroll
            for (int i = 0; i < 7; i++) sc[qq][i] = 0.f;

#pragma unroll 4
        for (int d = 0; d < 64; d += 4) {
            float4 q4[QB];
#pragma unroll
            for (int qq = 0; qq < QB; qq++)
                q4[qq] = *(const float4*)&Qw[qq * 64 + d];
#pragma unroll
            for (int i = 0; i < 7; i++) {
                int k = lane + 32 * i;
                float4 kv = *(const float4*)&Ksr[k * KSRP + d];
#pragma unroll
                for (int qq = 0; qq < QB; qq++)
                    sc[qq][i] += q4[qq].x * kv.x + q4[qq].y * kv.y
                               + q4[qq].z * kv.z + q4[qq].w * kv.w;
            }
        }

        float inv[QB];
#pragma unroll
        for (int qq = 0; qq < QB; qq++) {
            float m = -INFINITY;
#pragma unroll
            for (int i = 0; i < 7; i++) {
                int k = lane + 32 * i;
                if (k < SS) {
                    float v = sc[qq][i] * SCALEV;
                    if (k >= NP) v *= Co[k - NP];
                    sc[qq][i] = v;
                    m = fmaxf(m, v);
                } else sc[qq][i] = -INFINITY;
            }
#pragma unroll
            for (int o = 16; o; o >>= 1) m = fmaxf(m, __shfl_xor_sync(0xffffffffu, m, o));
            float ssum = 0.f;
#pragma unroll
            for (int i = 0; i < 7; i++) {
                int k = lane + 32 * i;
                float p = __expf(sc[qq][i] - m);
                if (k < SS) { ssum += p; Aw[qq * ARP + k] = p; }
                else if (k < ARP) Aw[qq * ARP + k] = 0.f;
            }
#pragma unroll
            for (int o = 16; o; o >>= 1) ssum += __shfl_xor_sync(0xffffffffu, ssum, o);
            inv[qq] = 1.f / ssum;
        }
        __syncwarp();

        float o1[QB], o2[QB];
#pragma unroll
        for (int qq = 0; qq < QB; qq++) { o1[qq] = 0.f; o2[qq] = 0.f; }
#pragma unroll 2
        for (int k0 = 0; k0 < ARP; k0 += 4) {
            float4 v1 = *(const float4*)&Vst[lane * VSTP + k0];
            float4 v2 = *(const float4*)&Vst[(lane + 32) * VSTP + k0];
#pragma unroll
            for (int qq = 0; qq < QB; qq++) {
                float4 a4 = *(const float4*)&Aw[qq * ARP + k0];
                o1[qq] += a4.x * v1.x + a4.y * v1.y + a4.z * v1.z + a4.w * v1.w;
                o2[qq] += a4.x * v2.x + a4.y * v2.y + a4.z * v2.z + a4.w * v2.w;
            }
        }
#pragma unroll
        for (int qq = 0; qq < QB; qq++) {
            int q = q0 + qq;
            if (q < SS) {
                __half* orow = outp + (size_t)(b * SS + q) * EE + h * HD;
                orow[lane]      = __float2half_rn(o1[qq] * inv[qq]);
                orow[lane + 32] = __float2half_rn(o2[qq] * inv[qq]);
            }
        }
        __syncwarp();
    }
}

// ---------------- host launch ----------------
extern "C" void kernel_launch(void* const* d_in, const int* in_sizes, int n_in,
                              void* d_out, int out_size)
{
    const float* x        = (const float*)d_in[0];
    const float* coeff    = (const float*)d_in[1];
    const float* patch_w  = (const float*)d_in[2];
    const float* patch_b  = (const float*)d_in[3];
    const float* cls      = (const float*)d_in[4];
    const float* pos      = (const float*)d_in[5];
    const float* lnpre_g  = (const float*)d_in[6];
    const float* lnpre_b  = (const float*)d_in[7];
    const float* prompts  = (const float*)d_in[8];
    const float* ln1_g    = (const float*)d_in[9];
    const float* ln1_b    = (const float*)d_in[10];
    const float* qkv_w    = (const float*)d_in[11];
    const float* qkv_b    = (const float*)d_in[12];
    const float* proj_w   = (const float*)d_in[13];
    const float* proj_b   = (const float*)d_in[14];
    const float* ln2_g    = (const float*)d_in[15];
    const float* ln2_b    = (const float*)d_in[16];
    const float* fc1_w    = (const float*)d_in[17];
    const float* fc1_b    = (const float*)d_in[18];
    const float* fc2_w    = (const float*)d_in[19];
    const float* fc2_b    = (const float*)d_in[20];
    const float* lnpost_g = (const float*)d_in[21];
    const float* lnpost_b = (const float*)d_in[22];
    float* out = (float*)d_out;

    float *p_h, *p_qkv, *p_o;
    __half *p_hh, *p_oh, *p_ffh, *p_wq, *p_wp, *p_w1, *p_w2, *p_wc;
    cudaGetSymbolAddress((void**)&p_h,   g_h);
    cudaGetSymbolAddress((void**)&p_hh,  g_hh);
    cudaGetSymbolAddress((void**)&p_qkv, g_qkv);
    cudaGetSymbolAddress((void**)&p_oh,  g_oh);
    cudaGetSymbolAddress((void**)&p_ffh, g_ffh);
    cudaGetSymbolAddress((void**)&p_o,   g_o);
    cudaGetSymbolAddress((void**)&p_wq,  g_wq);
    cudaGetSymbolAddress((void**)&p_wp,  g_wp);
    cudaGetSymbolAddress((void**)&p_w1,  g_w1);
    cudaGetSymbolAddress((void**)&p_w2,  g_w2);
    cudaGetSymbolAddress((void**)&p_wc,  g_wc);

    const int smAttn = SM_ATTN_FLOATS * (int)sizeof(float);
    cudaFuncSetAttribute(attn_kernel, cudaFuncAttributeMaxDynamicSharedMemorySize, smAttn);
    cudaFuncSetAttribute(hgemm_kernel, cudaFuncAttributeMaxDynamicSharedMemorySize, TG_SMEM);

    // convert all weights to fp16 once
    {
        int n;
        n = NL * 3 * EE * EE / 4; cvt_kernel<<<(n + 255) / 256, 256>>>(qkv_w,  p_wq, n);
        n = NL * EE * EE / 4;     cvt_kernel<<<(n + 255) / 256, 256>>>(proj_w, p_wp, n);
        n = NL * FFD * EE / 4;    cvt_kernel<<<(n + 255) / 256, 256>>>(fc1_w,  p_w1, n);
        n = NL * EE * FFD / 4;    cvt_kernel<<<(n + 255) / 256, 256>>>(fc2_w,  p_w2, n);
        n = EE * EE / 4;          cvt_kernel<<<(n + 255) / 256, 256>>>(patch_w, p_wc, n);
    }

    // patch embedding: im2col (half) -> hgemm -> fp32 conv out
    im2col_kernel<<<(MCONV * EE + 255) / 256, 256>>>(x, p_ffh);
    hgemm_kernel<<<dim3(EE / 128, MCONV / 128), 256, TG_SMEM>>>(
        p_ffh, p_wc, patch_b, p_o, (__half*)0, MCONV, EE, EE, 0);

    lnpre_kernel<<<BB * NP, 256>>>(p_o, cls, pos, lnpre_g, lnpre_b, p_h);

    const int mt = (BS + 127) / 128;   // 54
    for (int l = 0; l < NL; l++) {
        ln1_kernel<<<BS, 256>>>(p_h, prompts + (size_t)l * NPR * EE,
                                ln1_g + l * EE, ln1_b + l * EE, p_h, p_hh);
        hgemm_kernel<<<dim3(3 * EE / 128, mt), 256, TG_SMEM>>>(
            p_hh, p_wq + (size_t)l * 3 * EE * EE, qkv_b + (size_t)l * 3 * EE,
            p_qkv, (__half*)0, BS, 3 * EE, EE, 0);
        attn_kernel<<<BB * NH, 256, smAttn>>>(p_qkv, coeff + (size_t)l * NPR, p_oh);
        hgemm_kernel<<<dim3(EE / 128, mt), 256, TG_SMEM>>>(
            p_oh, p_wp + (size_t)l * EE * EE, proj_b + (size_t)l * EE,
            p_h, (__half*)0, BS, EE, EE, 2);
        ln_kernel<<<BS, 256>>>(p_h, ln2_g + l * EE, ln2_b + l * EE, p_hh);
        hgemm_kernel<<<dim3(FFD / 128, mt), 256, TG_SMEM>>>(
            p_hh, p_w1 + (size_t)l * FFD * EE, fc1_b + (size_t)l * FFD,
            (float*)0, p_ffh, BS, FFD, EE, 1);
        hgemm_kernel<<<dim3(EE / 128, mt), 256, TG_SMEM>>>(
            p_ffh, p_w2 + (size_t)l * EE * FFD, fc2_b + (size_t)l * EE,
            p_h, (__half*)0, BS, EE, FFD, 2);
    }

    lnpost_kernel<<<BB, 256>>>(p_h, lnpost_g, lnpost_b, out);
}

// round 11
// speedup vs baseline: 7.4246x; 1.4091x over previous
#include <cuda_runtime.h>
#include <cuda_fp16.h>
#include <math.h>
#include <stdint.h>

// ---------------- geometry ----------------
#define BB     32
#define CCH    3
#define IMG    224
#define PTCH   16
#define EE     768
#define NH     12
#define NL     12
#define NPR    16
#define NP     197
#define SS     213
#define HD     64
#define FFD    3072
#define EPSV   1e-6f
#define SCALEV 0.125f

#define BS      (BB * SS)          // 6816
#define NPATCH  196
#define MCONV   (BB * NPATCH)      // 6272

// ---------------- scratch (device globals: allowed) ----------------
__device__ float  g_h  [(size_t)BS * EE];          // fp32 residual stream
__device__ __half g_hh [(size_t)BS * EE];          // LN outputs (half)
__device__ __half g_qkvh[(size_t)BS * 3 * EE];     // qkv (half)
__device__ __half g_oh [(size_t)BS * EE];          // attention out (half)
__device__ __half g_ffh[(size_t)BS * FFD];         // fc1 out / im2col (half)
__device__ float  g_o  [(size_t)BS * EE];          // conv out (fp32)
// fp16 weight copies
__device__ __half g_wq [(size_t)NL * 3 * EE * EE];
__device__ __half g_wp [(size_t)NL * EE * EE];
__device__ __half g_w1 [(size_t)NL * FFD * EE];
__device__ __half g_w2 [(size_t)NL * EE * FFD];
__device__ __half g_wc [(size_t)EE * EE];

// ---------------- helpers ----------------
__device__ __forceinline__ float blk_sum(float v) {
    __shared__ float red[8];
    __shared__ float tot;
    int lane = threadIdx.x & 31, w = threadIdx.x >> 5;
#pragma unroll
    for (int o = 16; o; o >>= 1) v += __shfl_xor_sync(0xffffffffu, v, o);
    if (lane == 0) red[w] = v;
    __syncthreads();
    if (w == 0) {
        float t = (lane < 8) ? red[lane] : 0.f;
#pragma unroll
        for (int o = 4; o; o >>= 1) t += __shfl_xor_sync(0xffffffffu, t, o);
        if (lane == 0) tot = t;
    }
    __syncthreads();
    return tot;
}

__device__ __forceinline__ void cpa16_s(uint32_t dst, const void* src, int srcBytes) {
    asm volatile("cp.async.cg.shared.global [%0], [%1], 16, %2;"
                 :: "r"(dst), "l"(src), "r"(srcBytes));
}

__device__ __forceinline__ uint32_t lds32(uint32_t a) {
    uint32_t v;
    asm volatile("ld.shared.b32 %0, [%1];" : "=r"(v) : "r"(a));
    return v;
}

__device__ __forceinline__ void mma16816(float* d, const uint32_t* a, const uint32_t* b) {
    asm volatile(
        "mma.sync.aligned.m16n8k16.row.col.f32.f16.f16.f32 "
        "{%0,%1,%2,%3}, {%4,%5,%6,%7}, {%8,%9}, {%0,%1,%2,%3};"
        : "+f"(d[0]), "+f"(d[1]), "+f"(d[2]), "+f"(d[3])
        : "r"(a[0]), "r"(a[1]), "r"(a[2]), "r"(a[3]), "r"(b[0]), "r"(b[1]));
}

// ---------------- weight fp16 convert ----------------
__global__ void cvt_kernel(const float* __restrict__ src, __half* __restrict__ dst, int n4) {
    int i = blockIdx.x * 256 + threadIdx.x;
    if (i >= n4) return;
    float4 v = ((const float4*)src)[i];
    ((__half2*)dst)[2 * i]     = __floats2half2_rn(v.x, v.y);
    ((__half2*)dst)[2 * i + 1] = __floats2half2_rn(v.z, v.w);
}

// ---------------- im2col (half out) ----------------
__global__ void im2col_kernel(const float* __restrict__ x, __half* __restrict__ out) {
    int idx = blockIdx.x * 256 + threadIdx.x;
    if (idx >= MCONV * EE) return;
    int m = idx / EE;
    int k = idx % EE;
    int b = m / NPATCH, p = m % NPATCH;
    int c = k >> 8, rem = k & 255, i = rem >> 4, j = rem & 15;
    int py = p / 14, px = p % 14;
    out[idx] = __float2half_rn(
        x[(((size_t)b * CCH + c) * IMG + (py * PTCH + i)) * IMG + (px * PTCH + j)]);
}

// ---------------- FP16 tensor GEMM (mma.sync m16n8k16), 3-stage cp.async ----
// epi 0: fp32 out ; epi 1: bias+GELU -> half ; epi 2: bias+residual fp32 ; epi 3: bias -> half
#define KT        64
#define RSB       144
#define MAT_BYTES (128 * RSB)
#define STG_BYTES (2 * MAT_BYTES)
#define NSTAGE    3
#define TG_SMEM   (NSTAGE * STG_BYTES)

__global__ __launch_bounds__(256)
void hgemm_kernel(const __half* __restrict__ A, const __half* __restrict__ Bw,
                  const float* __restrict__ bias, float* __restrict__ Cf,
                  __half* __restrict__ Ch, int M, int N, int K, int epi)
{
    extern __shared__ char smg[];
    const uint32_t smem_base = (uint32_t)__cvta_generic_to_shared(smg);
    const int tid  = threadIdx.x;
    const int warp = tid >> 5, lane = tid & 31;
    const int wm = warp >> 2;
    const int wn = warp & 3;
    const int r  = lane >> 2;
    const int cg = lane & 3;
    const int row0 = blockIdx.y * 128;
    const int col0 = blockIdx.x * 128;

    float acc[4][4][4];
#pragma unroll
    for (int mi = 0; mi < 4; mi++)
#pragma unroll
        for (int ni = 0; ni < 4; ni++)
#pragma unroll
            for (int e = 0; e < 4; e++) acc[mi][ni][e] = 0.f;

    const int frow   = tid >> 3;
    const int fcol16 = tid & 7;
    const int nc = K / KT;

#define FILL(sidx, kk0)                                                          \
    {                                                                            \
        uint32_t sA = smem_base + (sidx) * STG_BYTES;                            \
        uint32_t sB = sA + MAT_BYTES;                                            \
        _Pragma("unroll")                                                        \
        for (int c = 0; c < 4; c++) {                                            \
            int row = frow + c * 32;                                             \
            uint32_t doff = (uint32_t)row * RSB + fcol16 * 16;                   \
            cpa16_s(sA + doff, A + (size_t)(row0 + row) * K + (kk0) + fcol16 * 8,\
                    (row0 + row < M) ? 16 : 0);                                  \
            cpa16_s(sB + doff, Bw + (size_t)(col0 + row) * K + (kk0) + fcol16 * 8, 16);\
        }                                                                        \
        asm volatile("cp.async.commit_group;");                                  \
    }

    FILL(0, 0);
    if (nc > 1) FILL(1, KT);

    for (int i = 0; i < nc; i++) {
        if (i + 2 < nc) {
            FILL((i + 2) % NSTAGE, (i + 2) * KT);
            asm volatile("cp.async.wait_group 2;");
        } else if (i + 1 < nc) {
            asm volatile("cp.async.wait_group 1;");
        } else {
            asm volatile("cp.async.wait_group 0;");
        }
        __syncthreads();

        const uint32_t sA = smem_base + (i % NSTAGE) * STG_BYTES;
        const uint32_t sB = sA + MAT_BYTES;
#pragma unroll
        for (int kk = 0; kk < KT; kk += 16) {
            uint32_t af[4][4], bf[4][2];
#pragma unroll
            for (int mi = 0; mi < 4; mi++) {
                uint32_t base = sA + (uint32_t)(wm * 64 + mi * 16 + r) * RSB + (kk + 2 * cg) * 2;
                af[mi][0] = lds32(base);
                af[mi][1] = lds32(base + 8 * RSB);
                af[mi][2] = lds32(base + 16);
                af[mi][3] = lds32(base + 8 * RSB + 16);
            }
#pragma unroll
            for (int ni = 0; ni < 4; ni++) {
                uint32_t base = sB + (uint32_t)(wn * 32 + ni * 8 + r) * RSB + (kk + 2 * cg) * 2;
                bf[ni][0] = lds32(base);
                bf[ni][1] = lds32(base + 16);
            }
#pragma unroll
            for (int mi = 0; mi < 4; mi++)
#pragma unroll
                for (int ni = 0; ni < 4; ni++)
                    mma16816(acc[mi][ni], af[mi], bf[ni]);
        }
        __syncthreads();
    }
#undef FILL

#pragma unroll
    for (int mi = 0; mi < 4; mi++) {
        int mr0 = row0 + wm * 64 + mi * 16 + r;
#pragma unroll
        for (int ni = 0; ni < 4; ni++) {
            int nc2 = col0 + wn * 32 + ni * 8 + 2 * cg;
            float b0 = bias[nc2], b1 = bias[nc2 + 1];
#pragma unroll
            for (int half_ = 0; half_ < 2; half_++) {
                int rr = mr0 + half_ * 8;
                if (rr >= M) continue;
                float v0 = acc[mi][ni][half_ * 2 + 0] + b0;
                float v1 = acc[mi][ni][half_ * 2 + 1] + b1;
                size_t idx = (size_t)rr * N + nc2;
                if (epi == 1) {
                    v0 = 0.5f * v0 * (1.f + erff(v0 * 0.70710678118654752f));
                    v1 = 0.5f * v1 * (1.f + erff(v1 * 0.70710678118654752f));
                    *(__half2*)&Ch[idx] = __floats2half2_rn(v0, v1);
                } else if (epi == 3) {
                    *(__half2*)&Ch[idx] = __floats2half2_rn(v0, v1);
                } else {
                    if (epi == 2) { v0 += Cf[idx]; v1 += Cf[idx + 1]; }
                    Cf[idx] = v0; Cf[idx + 1] = v1;
                }
            }
        }
    }
}

// ---------------- LN kernels ----------------
__global__ void lnpre_kernel(const float* __restrict__ conv, const float* __restrict__ cls,
                             const float* __restrict__ pos, const float* __restrict__ g,
                             const float* __restrict__ bb, float* __restrict__ dst)
{
    int row = blockIdx.x;
    int b = row / NP, s = row % NP;
    int t = threadIdx.x;
    const float* base = (s == 0) ? cls : conv + (size_t)(b * NPATCH + s - 1) * EE;
    const float* pr = pos + (size_t)s * EE;
    float x0 = base[t] + pr[t];
    float x1 = base[t + 256] + pr[t + 256];
    float x2 = base[t + 512] + pr[t + 512];
    float mean = blk_sum(x0 + x1 + x2) * (1.f / EE);
    float d0 = x0 - mean, d1 = x1 - mean, d2 = x2 - mean;
    float var = blk_sum(d0 * d0 + d1 * d1 + d2 * d2) * (1.f / EE);
    float rs = rsqrtf(var + EPSV);
    float* o = dst + (size_t)(b * SS + s) * EE;
    o[t]       = d0 * rs * g[t]       + bb[t];
    o[t + 256] = d1 * rs * g[t + 256] + bb[t + 256];
    o[t + 512] = d2 * rs * g[t + 512] + bb[t + 512];
}

__global__ void ln1_kernel(const float* __restrict__ src, const float* __restrict__ prompt,
                           const float* __restrict__ g, const float* __restrict__ bb,
                           float* __restrict__ hwr, __half* __restrict__ dst)
{
    int row = blockIdx.x;
    int s = row % SS;
    int t = threadIdx.x;
    const float* in = (s < NP) ? src + (size_t)row * EE
                               : prompt + (size_t)(s - NP) * EE;
    float x0 = in[t], x1 = in[t + 256], x2 = in[t + 512];
    if (s >= NP) {
        float* hw = hwr + (size_t)row * EE;
        hw[t] = x0; hw[t + 256] = x1; hw[t + 512] = x2;
    }
    float mean = blk_sum(x0 + x1 + x2) * (1.f / EE);
    float d0 = x0 - mean, d1 = x1 - mean, d2 = x2 - mean;
    float var = blk_sum(d0 * d0 + d1 * d1 + d2 * d2) * (1.f / EE);
    float rs = rsqrtf(var + EPSV);
    __half* o = dst + (size_t)row * EE;
    o[t]       = __float2half_rn(d0 * rs * g[t]       + bb[t]);
    o[t + 256] = __float2half_rn(d1 * rs * g[t + 256] + bb[t + 256]);
    o[t + 512] = __float2half_rn(d2 * rs * g[t + 512] + bb[t + 512]);
}

__global__ void ln_kernel(const float* __restrict__ src, const float* __restrict__ g,
                          const float* __restrict__ bb, __half* __restrict__ dst)
{
    int row = blockIdx.x;
    int t = threadIdx.x;
    const float* in = src + (size_t)row * EE;
    float x0 = in[t], x1 = in[t + 256], x2 = in[t + 512];
    float mean = blk_sum(x0 + x1 + x2) * (1.f / EE);
    float d0 = x0 - mean, d1 = x1 - mean, d2 = x2 - mean;
    float var = blk_sum(d0 * d0 + d1 * d1 + d2 * d2) * (1.f / EE);
    float rs = rsqrtf(var + EPSV);
    __half* o = dst + (size_t)row * EE;
    o[t]       = __float2half_rn(d0 * rs * g[t]       + bb[t]);
    o[t + 256] = __float2half_rn(d1 * rs * g[t + 256] + bb[t + 256]);
    o[t + 512] = __float2half_rn(d2 * rs * g[t + 512] + bb[t + 512]);
}

__global__ void lnpost_kernel(const float* __restrict__ src, const float* __restrict__ g,
                              const float* __restrict__ bb, float* __restrict__ dst)
{
    int b = blockIdx.x;
    int t = threadIdx.x;
    const float* in = src + (size_t)(b * SS) * EE;
    float x0 = in[t], x1 = in[t + 256], x2 = in[t + 512];
    float mean = blk_sum(x0 + x1 + x2) * (1.f / EE);
    float d0 = x0 - mean, d1 = x1 - mean, d2 = x2 - mean;
    float var = blk_sum(d0 * d0 + d1 * d1 + d2 * d2) * (1.f / EE);
    float rs = rsqrtf(var + EPSV);
    float* o = dst + (size_t)b * EE;
    o[t]       = d0 * rs * g[t]       + bb[t];
    o[t + 256] = d1 * rs * g[t + 256] + bb[t + 256];
    o[t + 512] = d2 * rs * g[t + 512] + bb[t + 512];
}

// ---------------- tensor-core flash attention ----------------
// one block per (b,h); K [224][72]h, V^T [64][232]h, Q staged per warp [16][72]h
#define KHW 36                              // Kh row stride in half2 words
#define VTW 116                             // Vt row stride in half2 words
#define AT_SMEM ((224 * 72 + 64 * 232 + 8 * 16 * 72) * 2 + 224 * 8)

__global__ __launch_bounds__(256)
void attn_kernel(const __half* __restrict__ qkvh,
                 const float* __restrict__ coeff,
                 __half* __restrict__ outp)
{
    extern __shared__ char smraw[];
    __half* Kh = (__half*)smraw;                 // [224][72]
    __half* Vt = Kh + 224 * 72;                  // [64][232]
    __half* Qs = Vt + 64 * 232;                  // [8][16][72]
    float*  fac = (float*)(Qs + 8 * 16 * 72);    // [224]
    float*  nb  = fac + 224;                     // [224]

    const int bh = blockIdx.x;
    const int b = bh / NH, h = bh % NH;
    const int tid = threadIdx.x;
    const int w = tid >> 5, lane = tid & 31;
    const int r = lane >> 2, cg = lane & 3;
    const __half* base = qkvh + (size_t)b * SS * (3 * EE) + h * HD;

    if (tid < 224) {
        float f = 0.f, nbv = -1e30f;
        if (tid < NP)      { f = SCALEV; nbv = 0.f; }
        else if (tid < SS) { f = SCALEV * coeff[tid - NP]; nbv = 0.f; }
        fac[tid] = f; nb[tid] = nbv;
    }
    for (int idx = tid; idx < 224 * 32; idx += 256) {
        int s = idx >> 5, d2 = idx & 31;
        __half2 kv = (s < SS) ? *(const __half2*)(base + (size_t)s * (3 * EE) + EE + 2 * d2)
                              : __floats2half2_rn(0.f, 0.f);
        *(__half2*)(Kh + s * 72 + 2 * d2) = kv;
        __half2 vv = (s < SS) ? *(const __half2*)(base + (size_t)s * (3 * EE) + 2 * EE + 2 * d2)
                              : __floats2half2_rn(0.f, 0.f);
        Vt[(2 * d2) * 232 + s]     = __low2half(vv);
        Vt[(2 * d2 + 1) * 232 + s] = __high2half(vv);
    }
    __syncthreads();

    const uint32_t KhU = (uint32_t)__cvta_generic_to_shared(Kh);
    const uint32_t VtU = (uint32_t)__cvta_generic_to_shared(Vt);
    const uint32_t QsU = (uint32_t)__cvta_generic_to_shared(Qs) + w * (16 * 72 * 2);

    for (int q0 = w * 16; q0 < 224; q0 += 128) {
        // stage Q tile
        for (int idx = lane; idx < 16 * 32; idx += 32) {
            int row = idx >> 5, d2 = idx & 31;
            int q = q0 + row;
            __half2 qv = (q < SS) ? *(const __half2*)(base + (size_t)q * (3 * EE) + 2 * d2)
                                  : __floats2half2_rn(0.f, 0.f);
            *(__half2*)(Qs + (w * 16 + row) * 72 + 2 * d2) = qv;
        }
        __syncwarp();

        uint32_t qf[4][4];
#pragma unroll
        for (int ks = 0; ks < 4; ks++) {
            uint32_t c = cg + 8 * ks;
            qf[ks][0] = lds32(QsU + (r * KHW + c) * 4);
            qf[ks][1] = lds32(QsU + ((r + 8) * KHW + c) * 4);
            qf[ks][2] = lds32(QsU + (r * KHW + c + 4) * 4);
            qf[ks][3] = lds32(QsU + ((r + 8) * KHW + c + 4) * 4);
        }

        float m0 = -INFINITY, m1 = -INFINITY, l0 = 0.f, l1 = 0.f;
        float ao[8][4];
#pragma unroll
        for (int nt = 0; nt < 8; nt++)
#pragma unroll
            for (int e = 0; e < 4; e++) ao[nt][e] = 0.f;

        for (int kt = 0; kt < 14; kt++) {
            float sa[2][4];
#pragma unroll
            for (int ns = 0; ns < 2; ns++)
#pragma unroll
                for (int e = 0; e < 4; e++) sa[ns][e] = 0.f;

#pragma unroll
            for (int ks = 0; ks < 4; ks++) {
#pragma unroll
                for (int ns = 0; ns < 2; ns++) {
                    uint32_t kb[2];
                    uint32_t rowa = (uint32_t)(kt * 16 + ns * 8 + r) * KHW + cg + 8 * ks;
                    kb[0] = lds32(KhU + rowa * 4);
                    kb[1] = lds32(KhU + (rowa + 4) * 4);
                    mma16816(sa[ns], qf[ks], kb);
                }
            }

            // scale + bias + softmax update
            float p[2][4];
            float tm0 = -INFINITY, tm1 = -INFINITY;
#pragma unroll
            for (int ns = 0; ns < 2; ns++) {
                int c0 = kt * 16 + ns * 8 + 2 * cg;
                float f0 = fac[c0], f1 = fac[c0 + 1];
                float n0 = nb[c0],  n1 = nb[c0 + 1];
                sa[ns][0] = sa[ns][0] * f0 + n0;
                sa[ns][1] = sa[ns][1] * f1 + n1;
                sa[ns][2] = sa[ns][2] * f0 + n0;
                sa[ns][3] = sa[ns][3] * f1 + n1;
                tm0 = fmaxf(tm0, fmaxf(sa[ns][0], sa[ns][1]));
                tm1 = fmaxf(tm1, fmaxf(sa[ns][2], sa[ns][3]));
            }
#pragma unroll
            for (int o = 1; o <= 2; o <<= 1) {
                tm0 = fmaxf(tm0, __shfl_xor_sync(0xffffffffu, tm0, o));
                tm1 = fmaxf(tm1, __shfl_xor_sync(0xffffffffu, tm1, o));
            }
            float mn0 = fmaxf(m0, tm0), mn1 = fmaxf(m1, tm1);
            float sc0 = __expf(m0 - mn0), sc1 = __expf(m1 - mn1);
            float rs0 = 0.f, rs1 = 0.f;
#pragma unroll
            for (int ns = 0; ns < 2; ns++) {
                p[ns][0] = __expf(sa[ns][0] - mn0);
                p[ns][1] = __expf(sa[ns][1] - mn0);
                p[ns][2] = __expf(sa[ns][2] - mn1);
                p[ns][3] = __expf(sa[ns][3] - mn1);
                rs0 += p[ns][0] + p[ns][1];
                rs1 += p[ns][2] + p[ns][3];
            }
#pragma unroll
            for (int o = 1; o <= 2; o <<= 1) {
                rs0 += __shfl_xor_sync(0xffffffffu, rs0, o);
                rs1 += __shfl_xor_sync(0xffffffffu, rs1, o);
            }
            l0 = l0 * sc0 + rs0; l1 = l1 * sc1 + rs1;
            m0 = mn0; m1 = mn1;

            uint32_t pf[4];
            __half2 ph;
            ph = __floats2half2_rn(p[0][0], p[0][1]); pf[0] = *(uint32_t*)&ph;
            ph = __floats2half2_rn(p[0][2], p[0][3]); pf[1] = *(uint32_t*)&ph;
            ph = __floats2half2_rn(p[1][0], p[1][1]); pf[2] = *(uint32_t*)&ph;
            ph = __floats2half2_rn(p[1][2], p[1][3]); pf[3] = *(uint32_t*)&ph;

#pragma unroll
            for (int nt = 0; nt < 8; nt++) {
                ao[nt][0] *= sc0; ao[nt][1] *= sc0;
                ao[nt][2] *= sc1; ao[nt][3] *= sc1;
                uint32_t vb[2];
                uint32_t rowa = (uint32_t)(nt * 8 + r) * VTW + kt * 8 + cg;
                vb[0] = lds32(VtU + rowa * 4);
                vb[1] = lds32(VtU + (rowa + 4) * 4);
                mma16816(ao[nt], pf, vb);
            }
        }

        float inv0 = 1.f / l0, inv1 = 1.f / l1;
        int q = q0 + r;
        if (q < SS) {
            __half* orow = outp + (size_t)(b * SS + q) * EE + h * HD;
#pragma unroll
            for (int nt = 0; nt < 8; nt++)
                *(__half2*)&orow[nt * 8 + 2 * cg] =
                    __floats2half2_rn(ao[nt][0] * inv0, ao[nt][1] * inv0);
        }
        int q2 = q0 + 8 + r;
        if (q2 < SS) {
            __half* orow = outp + (size_t)(b * SS + q2) * EE + h * HD;
#pragma unroll
            for (int nt = 0; nt < 8; nt++)
                *(__half2*)&orow[nt * 8 + 2 * cg] =
                    __floats2half2_rn(ao[nt][2] * inv1, ao[nt][3] * inv1);
        }
    }
}

// ---------------- host launch ----------------
extern "C" void kernel_launch(void* const* d_in, const int* in_sizes, int n_in,
                              void* d_out, int out_size)
{
    const float* x        = (const float*)d_in[0];
    const float* coeff    = (const float*)d_in[1];
    const float* patch_w  = (const float*)d_in[2];
    const float* patch_b  = (const float*)d_in[3];
    const float* cls      = (const float*)d_in[4];
    const float* pos      = (const float*)d_in[5];
    const float* lnpre_g  = (const float*)d_in[6];
    const float* lnpre_b  = (const float*)d_in[7];
    const float* prompts  = (const float*)d_in[8];
    const float* ln1_g    = (const float*)d_in[9];
    const float* ln1_b    = (const float*)d_in[10];
    const float* qkv_w    = (const float*)d_in[11];
    const float* qkv_b    = (const float*)d_in[12];
    const float* proj_w   = (const float*)d_in[13];
    const float* proj_b   = (const float*)d_in[14];
    const float* ln2_g    = (const float*)d_in[15];
    const float* ln2_b    = (const float*)d_in[16];
    const float* fc1_w    = (const float*)d_in[17];
    const float* fc1_b    = (const float*)d_in[18];
    const float* fc2_w    = (const float*)d_in[19];
    const float* fc2_b    = (const float*)d_in[20];
    const float* lnpost_g = (const float*)d_in[21];
    const float* lnpost_b = (const float*)d_in[22];
    float* out = (float*)d_out;

    float *p_h, *p_o;
    __half *p_hh, *p_qkvh, *p_oh, *p_ffh, *p_wq, *p_wp, *p_w1, *p_w2, *p_wc;
    cudaGetSymbolAddress((void**)&p_h,    g_h);
    cudaGetSymbolAddress((void**)&p_hh,   g_hh);
    cudaGetSymbolAddress((void**)&p_qkvh, g_qkvh);
    cudaGetSymbolAddress((void**)&p_oh,   g_oh);
    cudaGetSymbolAddress((void**)&p_ffh,  g_ffh);
    cudaGetSymbolAddress((void**)&p_o,    g_o);
    cudaGetSymbolAddress((void**)&p_wq,   g_wq);
    cudaGetSymbolAddress((void**)&p_wp,   g_wp);
    cudaGetSymbolAddress((void**)&p_w1,   g_w1);
    cudaGetSymbolAddress((void**)&p_w2,   g_w2);
    cudaGetSymbolAddress((void**)&p_wc,   g_wc);

    cudaFuncSetAttribute(attn_kernel, cudaFuncAttributeMaxDynamicSharedMemorySize, AT_SMEM);
    cudaFuncSetAttribute(hgemm_kernel, cudaFuncAttributeMaxDynamicSharedMemorySize, TG_SMEM);

    {
        int n;
        n = NL * 3 * EE * EE / 4; cvt_kernel<<<(n + 255) / 256, 256>>>(qkv_w,  p_wq, n);
        n = NL * EE * EE / 4;     cvt_kernel<<<(n + 255) / 256, 256>>>(proj_w, p_wp, n);
        n = NL * FFD * EE / 4;    cvt_kernel<<<(n + 255) / 256, 256>>>(fc1_w,  p_w1, n);
        n = NL * EE * FFD / 4;    cvt_kernel<<<(n + 255) / 256, 256>>>(fc2_w,  p_w2, n);
        n = EE * EE / 4;          cvt_kernel<<<(n + 255) / 256, 256>>>(patch_w, p_wc, n);
    }

    im2col_kernel<<<(MCONV * EE + 255) / 256, 256>>>(x, p_ffh);
    hgemm_kernel<<<dim3(EE / 128, MCONV / 128), 256, TG_SMEM>>>(
        p_ffh, p_wc, patch_b, p_o, (__half*)0, MCONV, EE, EE, 0);

    lnpre_kernel<<<BB * NP, 256>>>(p_o, cls, pos, lnpre_g, lnpre_b, p_h);

    const int mt = (BS + 127) / 128;   // 54
    for (int l = 0; l < NL; l++) {
        ln1_kernel<<<BS, 256>>>(p_h, prompts + (size_t)l * NPR * EE,
                                ln1_g + l * EE, ln1_b + l * EE, p_h, p_hh);
        hgemm_kernel<<<dim3(3 * EE / 128, mt), 256, TG_SMEM>>>(
            p_hh, p_wq + (size_t)l * 3 * EE * EE, qkv_b + (size_t)l * 3 * EE,
            (float*)0, p_qkvh, BS, 3 * EE, EE, 3);
        attn_kernel<<<BB * NH, 256, AT_SMEM>>>(p_qkvh, coeff + (size_t)l * NPR, p_oh);
        hgemm_kernel<<<dim3(EE / 128, mt), 256, TG_SMEM>>>(
            p_oh, p_wp + (size_t)l * EE * EE, proj_b + (size_t)l * EE,
            p_h, (__half*)0, BS, EE, EE, 2);
        ln_kernel<<<BS, 256>>>(p_h, ln2_g + l * EE, ln2_b + l * EE, p_hh);
        hgemm_kernel<<<dim3(FFD / 128, mt), 256, TG_SMEM>>>(
            p_hh, p_w1 + (size_t)l * FFD * EE, fc1_b + (size_t)l * FFD,
            (float*)0, p_ffh, BS, FFD, EE, 1);
        hgemm_kernel<<<dim3(EE / 128, mt), 256, TG_SMEM>>>(
            p_ffh, p_w2 + (size_t)l * EE * FFD, fc2_b + (size_t)l * EE,
            p_h, (__half*)0, BS, EE, FFD, 2);
    }

    lnpost_kernel<<<BB, 256>>>(p_h, lnpost_g, lnpost_b, out);
}

// round 12
// speedup vs baseline: 7.8340x; 1.0551x over previous
#include <cuda_runtime.h>
#include <cuda_fp16.h>
#include <math.h>
#include <stdint.h>

// ---------------- geometry ----------------
#define BB     32
#define CCH    3
#define IMG    224
#define PTCH   16
#define EE     768
#define NH     12
#define NL     12
#define NPR    16
#define NP     197
#define SS     213
#define HD     64
#define FFD    3072
#define EPSV   1e-6f
#define SCALEV 0.125f

#define BS      (BB * SS)          // 6816
#define NPATCH  196
#define MCONV   (BB * NPATCH)      // 6272

// ---------------- scratch (device globals: allowed) ----------------
__device__ float  g_h  [(size_t)BS * EE];          // fp32 residual stream
__device__ __half g_hh [(size_t)BS * EE];          // LN outputs (half)
__device__ __half g_qkvh[(size_t)BS * 3 * EE];     // qkv (half)
__device__ __half g_oh [(size_t)BS * EE];          // attention out (half)
__device__ __half g_ffh[(size_t)BS * FFD];         // fc1 out / im2col (half)
__device__ float  g_o  [(size_t)BS * EE];          // conv out (fp32)
// fp16 weight copies
__device__ __half g_wq [(size_t)NL * 3 * EE * EE];
__device__ __half g_wp [(size_t)NL * EE * EE];
__device__ __half g_w1 [(size_t)NL * FFD * EE];
__device__ __half g_w2 [(size_t)NL * EE * FFD];
__device__ __half g_wc [(size_t)EE * EE];

// ---------------- helpers ----------------
__device__ __forceinline__ float blk_sum(float v) {
    __shared__ float red[8];
    __shared__ float tot;
    int lane = threadIdx.x & 31, w = threadIdx.x >> 5;
#pragma unroll
    for (int o = 16; o; o >>= 1) v += __shfl_xor_sync(0xffffffffu, v, o);
    if (lane == 0) red[w] = v;
    __syncthreads();
    if (w == 0) {
        float t = (lane < 8) ? red[lane] : 0.f;
#pragma unroll
        for (int o = 4; o; o >>= 1) t += __shfl_xor_sync(0xffffffffu, t, o);
        if (lane == 0) tot = t;
    }
    __syncthreads();
    return tot;
}

__device__ __forceinline__ void cpa16_s(uint32_t dst, const void* src, int srcBytes) {
    asm volatile("cp.async.cg.shared.global [%0], [%1], 16, %2;"
                 :: "r"(dst), "l"(src), "r"(srcBytes));
}

__device__ __forceinline__ uint32_t lds32(uint32_t a) {
    uint32_t v;
    asm volatile("ld.shared.b32 %0, [%1];" : "=r"(v) : "r"(a));
    return v;
}

__device__ __forceinline__ void ldsm4(uint32_t* d, uint32_t addr) {
    asm volatile("ldmatrix.sync.aligned.m8n8.x4.shared.b16 {%0,%1,%2,%3}, [%4];"
                 : "=r"(d[0]), "=r"(d[1]), "=r"(d[2]), "=r"(d[3]) : "r"(addr));
}

__device__ __forceinline__ void mma16816(float* d, const uint32_t* a, const uint32_t* b) {
    asm volatile(
        "mma.sync.aligned.m16n8k16.row.col.f32.f16.f16.f32 "
        "{%0,%1,%2,%3}, {%4,%5,%6,%7}, {%8,%9}, {%0,%1,%2,%3};"
        : "+f"(d[0]), "+f"(d[1]), "+f"(d[2]), "+f"(d[3])
        : "r"(a[0]), "r"(a[1]), "r"(a[2]), "r"(a[3]), "r"(b[0]), "r"(b[1]));
}

// ---------------- weight fp16 convert ----------------
__global__ void cvt_kernel(const float* __restrict__ src, __half* __restrict__ dst, int n4) {
    int i = blockIdx.x * 256 + threadIdx.x;
    if (i >= n4) return;
    float4 v = ((const float4*)src)[i];
    ((__half2*)dst)[2 * i]     = __floats2half2_rn(v.x, v.y);
    ((__half2*)dst)[2 * i + 1] = __floats2half2_rn(v.z, v.w);
}

// ---------------- im2col (half out) ----------------
__global__ void im2col_kernel(const float* __restrict__ x, __half* __restrict__ out) {
    int idx = blockIdx.x * 256 + threadIdx.x;
    if (idx >= MCONV * EE) return;
    int m = idx / EE;
    int k = idx % EE;
    int b = m / NPATCH, p = m % NPATCH;
    int c = k >> 8, rem = k & 255, i = rem >> 4, j = rem & 15;
    int py = p / 14, px = p % 14;
    out[idx] = __float2half_rn(
        x[(((size_t)b * CCH + c) * IMG + (py * PTCH + i)) * IMG + (px * PTCH + j)]);
}

// ---------------- FP16 tensor GEMM (mma.sync m16n8k16 + ldmatrix) ----------
// epi 0: fp32 out ; epi 1: bias+GELU -> half ; epi 2: bias+residual fp32 ; epi 3: bias -> half
#define KT        64
#define RSB       144
#define MAT_BYTES (128 * RSB)
#define STG_BYTES (2 * MAT_BYTES)
#define NSTAGE    3
#define TG_SMEM   (NSTAGE * STG_BYTES)

__global__ __launch_bounds__(256)
void hgemm_kernel(const __half* __restrict__ A, const __half* __restrict__ Bw,
                  const float* __restrict__ bias, float* __restrict__ Cf,
                  __half* __restrict__ Ch, int M, int N, int K, int epi)
{
    extern __shared__ char smg[];
    const uint32_t smem_base = (uint32_t)__cvta_generic_to_shared(smg);
    const int tid  = threadIdx.x;
    const int warp = tid >> 5, lane = tid & 31;
    const int wm = warp >> 2;
    const int wn = warp & 3;
    const int r  = lane >> 2;
    const int cg = lane & 3;
    const int row0 = blockIdx.y * 128;
    const int col0 = blockIdx.x * 128;

    // ldmatrix lane coords
    const int lg = lane >> 3;            // group 0..3
    const int lt = lane & 7;             // row-in-matrix

    float acc[4][4][4];
#pragma unroll
    for (int mi = 0; mi < 4; mi++)
#pragma unroll
        for (int ni = 0; ni < 4; ni++)
#pragma unroll
            for (int e = 0; e < 4; e++) acc[mi][ni][e] = 0.f;

    const int frow   = tid >> 3;
    const int fcol16 = tid & 7;
    const int nc = K / KT;

#define FILL(sidx, kk0)                                                          \
    {                                                                            \
        uint32_t sA = smem_base + (sidx) * STG_BYTES;                            \
        uint32_t sB = sA + MAT_BYTES;                                            \
        _Pragma("unroll")                                                        \
        for (int c = 0; c < 4; c++) {                                            \
            int row = frow + c * 32;                                             \
            uint32_t doff = (uint32_t)row * RSB + fcol16 * 16;                   \
            cpa16_s(sA + doff, A + (size_t)(row0 + row) * K + (kk0) + fcol16 * 8,\
                    (row0 + row < M) ? 16 : 0);                                  \
            cpa16_s(sB + doff, Bw + (size_t)(col0 + row) * K + (kk0) + fcol16 * 8, 16);\
        }                                                                        \
        asm volatile("cp.async.commit_group;");                                  \
    }

    FILL(0, 0);
    if (nc > 1) FILL(1, KT);

    for (int i = 0; i < nc; i++) {
        if (i + 2 < nc) {
            FILL((i + 2) % NSTAGE, (i + 2) * KT);
            asm volatile("cp.async.wait_group 2;");
        } else if (i + 1 < nc) {
            asm volatile("cp.async.wait_group 1;");
        } else {
            asm volatile("cp.async.wait_group 0;");
        }
        __syncthreads();

        const uint32_t sA = smem_base + (i % NSTAGE) * STG_BYTES;
        const uint32_t sB = sA + MAT_BYTES;
#pragma unroll
        for (int kk = 0; kk < KT; kk += 16) {
            uint32_t af[4][4], bB[2][4];
            // A fragments: matrices {r,k},{r+8,k},{r,k+8},{r+8,k+8}
#pragma unroll
            for (int mi = 0; mi < 4; mi++) {
                uint32_t addr = sA
                    + (uint32_t)(wm * 64 + mi * 16 + (lg & 1) * 8 + lt) * RSB
                    + (kk + (lg >> 1) * 8) * 2;
                ldsm4(af[mi], addr);
            }
            // B fragments: 2 ni per ldmatrix: {b0 even, b1 even, b0 odd, b1 odd}
#pragma unroll
            for (int ni2 = 0; ni2 < 2; ni2++) {
                uint32_t addr = sB
                    + (uint32_t)(wn * 32 + ni2 * 16 + (lg >> 1) * 8 + lt) * RSB
                    + (kk + (lg & 1) * 8) * 2;
                ldsm4(bB[ni2], addr);
            }
#pragma unroll
            for (int mi = 0; mi < 4; mi++)
#pragma unroll
                for (int ni = 0; ni < 4; ni++)
                    mma16816(acc[mi][ni], af[mi], &bB[ni >> 1][(ni & 1) * 2]);
        }
        __syncthreads();
    }
#undef FILL

#pragma unroll
    for (int mi = 0; mi < 4; mi++) {
        int mr0 = row0 + wm * 64 + mi * 16 + r;
#pragma unroll
        for (int ni = 0; ni < 4; ni++) {
            int nc2 = col0 + wn * 32 + ni * 8 + 2 * cg;
            float b0 = bias[nc2], b1 = bias[nc2 + 1];
#pragma unroll
            for (int half_ = 0; half_ < 2; half_++) {
                int rr = mr0 + half_ * 8;
                if (rr >= M) continue;
                float v0 = acc[mi][ni][half_ * 2 + 0] + b0;
                float v1 = acc[mi][ni][half_ * 2 + 1] + b1;
                size_t idx = (size_t)rr * N + nc2;
                if (epi == 1) {
                    v0 = 0.5f * v0 * (1.f + erff(v0 * 0.70710678118654752f));
                    v1 = 0.5f * v1 * (1.f + erff(v1 * 0.70710678118654752f));
                    *(__half2*)&Ch[idx] = __floats2half2_rn(v0, v1);
                } else if (epi == 3) {
                    *(__half2*)&Ch[idx] = __floats2half2_rn(v0, v1);
                } else {
                    if (epi == 2) { v0 += Cf[idx]; v1 += Cf[idx + 1]; }
                    Cf[idx] = v0; Cf[idx + 1] = v1;
                }
            }
        }
    }
}

// ---------------- LN kernels ----------------
__global__ void lnpre_kernel(const float* __restrict__ conv, const float* __restrict__ cls,
                             const float* __restrict__ pos, const float* __restrict__ g,
                             const float* __restrict__ bb, float* __restrict__ dst)
{
    int row = blockIdx.x;
    int b = row / NP, s = row % NP;
    int t = threadIdx.x;
    const float* base = (s == 0) ? cls : conv + (size_t)(b * NPATCH + s - 1) * EE;
    const float* pr = pos + (size_t)s * EE;
    float x0 = base[t] + pr[t];
    float x1 = base[t + 256] + pr[t + 256];
    float x2 = base[t + 512] + pr[t + 512];
    float mean = blk_sum(x0 + x1 + x2) * (1.f / EE);
    float d0 = x0 - mean, d1 = x1 - mean, d2 = x2 - mean;
    float var = blk_sum(d0 * d0 + d1 * d1 + d2 * d2) * (1.f / EE);
    float rs = rsqrtf(var + EPSV);
    float* o = dst + (size_t)(b * SS + s) * EE;
    o[t]       = d0 * rs * g[t]       + bb[t];
    o[t + 256] = d1 * rs * g[t + 256] + bb[t + 256];
    o[t + 512] = d2 * rs * g[t + 512] + bb[t + 512];
}

__global__ void ln1_kernel(const float* __restrict__ src, const float* __restrict__ prompt,
                           const float* __restrict__ g, const float* __restrict__ bb,
                           float* __restrict__ hwr, __half* __restrict__ dst)
{
    int row = blockIdx.x;
    int s = row % SS;
    int t = threadIdx.x;
    const float* in = (s < NP) ? src + (size_t)row * EE
                               : prompt + (size_t)(s - NP) * EE;
    float x0 = in[t], x1 = in[t + 256], x2 = in[t + 512];
    if (s >= NP) {
        float* hw = hwr + (size_t)row * EE;
        hw[t] = x0; hw[t + 256] = x1; hw[t + 512] = x2;
    }
    float mean = blk_sum(x0 + x1 + x2) * (1.f / EE);
    float d0 = x0 - mean, d1 = x1 - mean, d2 = x2 - mean;
    float var = blk_sum(d0 * d0 + d1 * d1 + d2 * d2) * (1.f / EE);
    float rs = rsqrtf(var + EPSV);
    __half* o = dst + (size_t)row * EE;
    o[t]       = __float2half_rn(d0 * rs * g[t]       + bb[t]);
    o[t + 256] = __float2half_rn(d1 * rs * g[t + 256] + bb[t + 256]);
    o[t + 512] = __float2half_rn(d2 * rs * g[t + 512] + bb[t + 512]);
}

__global__ void ln_kernel(const float* __restrict__ src, const float* __restrict__ g,
                          const float* __restrict__ bb, __half* __restrict__ dst)
{
    int row = blockIdx.x;
    int t = threadIdx.x;
    const float* in = src + (size_t)row * EE;
    float x0 = in[t], x1 = in[t + 256], x2 = in[t + 512];
    float mean = blk_sum(x0 + x1 + x2) * (1.f / EE);
    float d0 = x0 - mean, d1 = x1 - mean, d2 = x2 - mean;
    float var = blk_sum(d0 * d0 + d1 * d1 + d2 * d2) * (1.f / EE);
    float rs = rsqrtf(var + EPSV);
    __half* o = dst + (size_t)row * EE;
    o[t]       = __float2half_rn(d0 * rs * g[t]       + bb[t]);
    o[t + 256] = __float2half_rn(d1 * rs * g[t + 256] + bb[t + 256]);
    o[t + 512] = __float2half_rn(d2 * rs * g[t + 512] + bb[t + 512]);
}

__global__ void lnpost_kernel(const float* __restrict__ src, const float* __restrict__ g,
                              const float* __restrict__ bb, float* __restrict__ dst)
{
    int b = blockIdx.x;
    int t = threadIdx.x;
    const float* in = src + (size_t)(b * SS) * EE;
    float x0 = in[t], x1 = in[t + 256], x2 = in[t + 512];
    float mean = blk_sum(x0 + x1 + x2) * (1.f / EE);
    float d0 = x0 - mean, d1 = x1 - mean, d2 = x2 - mean;
    float var = blk_sum(d0 * d0 + d1 * d1 + d2 * d2) * (1.f / EE);
    float rs = rsqrtf(var + EPSV);
    float* o = dst + (size_t)b * EE;
    o[t]       = d0 * rs * g[t]       + bb[t];
    o[t + 256] = d1 * rs * g[t + 256] + bb[t + 256];
    o[t + 512] = d2 * rs * g[t + 512] + bb[t + 512];
}

// ---------------- tensor-core flash attention ----------------
#define KHW 36
#define VTW 116
#define AT_SMEM ((224 * 72 + 64 * 232 + 8 * 16 * 72) * 2 + 224 * 8)

__global__ __launch_bounds__(256)
void attn_kernel(const __half* __restrict__ qkvh,
                 const float* __restrict__ coeff,
                 __half* __restrict__ outp)
{
    extern __shared__ char smraw[];
    __half* Kh = (__half*)smraw;                 // [224][72]
    __half* Vt = Kh + 224 * 72;                  // [64][232]
    __half* Qs = Vt + 64 * 232;                  // [8][16][72]
    float*  fac = (float*)(Qs + 8 * 16 * 72);    // [224]
    float*  nb  = fac + 224;                     // [224]

    const int bh = blockIdx.x;
    const int b = bh / NH, h = bh % NH;
    const int tid = threadIdx.x;
    const int w = tid >> 5, lane = tid & 31;
    const int r = lane >> 2, cg = lane & 3;
    const __half* base = qkvh + (size_t)b * SS * (3 * EE) + h * HD;

    if (tid < 224) {
        float f = 0.f, nbv = -1e30f;
        if (tid < NP)      { f = SCALEV; nbv = 0.f; }
        else if (tid < SS) { f = SCALEV * coeff[tid - NP]; nbv = 0.f; }
        fac[tid] = f; nb[tid] = nbv;
    }
    for (int idx = tid; idx < 224 * 32; idx += 256) {
        int s = idx >> 5, d2 = idx & 31;
        __half2 kv = (s < SS) ? *(const __half2*)(base + (size_t)s * (3 * EE) + EE + 2 * d2)
                              : __floats2half2_rn(0.f, 0.f);
        *(__half2*)(Kh + s * 72 + 2 * d2) = kv;
        __half2 vv = (s < SS) ? *(const __half2*)(base + (size_t)s * (3 * EE) + 2 * EE + 2 * d2)
                              : __floats2half2_rn(0.f, 0.f);
        Vt[(2 * d2) * 232 + s]     = __low2half(vv);
        Vt[(2 * d2 + 1) * 232 + s] = __high2half(vv);
    }
    __syncthreads();

    const uint32_t KhU = (uint32_t)__cvta_generic_to_shared(Kh);
    const uint32_t VtU = (uint32_t)__cvta_generic_to_shared(Vt);
    const uint32_t QsU = (uint32_t)__cvta_generic_to_shared(Qs) + w * (16 * 72 * 2);

    for (int q0 = w * 16; q0 < 224; q0 += 128) {
        for (int idx = lane; idx < 16 * 32; idx += 32) {
            int row = idx >> 5, d2 = idx & 31;
            int q = q0 + row;
            __half2 qv = (q < SS) ? *(const __half2*)(base + (size_t)q * (3 * EE) + 2 * d2)
                                  : __floats2half2_rn(0.f, 0.f);
            *(__half2*)(Qs + (w * 16 + row) * 72 + 2 * d2) = qv;
        }
        __syncwarp();

        uint32_t qf[4][4];
#pragma unroll
        for (int ks = 0; ks < 4; ks++) {
            uint32_t c = cg + 8 * ks;
            qf[ks][0] = lds32(QsU + (r * KHW + c) * 4);
            qf[ks][1] = lds32(QsU + ((r + 8) * KHW + c) * 4);
            qf[ks][2] = lds32(QsU + (r * KHW + c + 4) * 4);
            qf[ks][3] = lds32(QsU + ((r + 8) * KHW + c + 4) * 4);
        }

        float m0 = -INFINITY, m1 = -INFINITY, l0 = 0.f, l1 = 0.f;
        float ao[8][4];
#pragma unroll
        for (int nt = 0; nt < 8; nt++)
#pragma unroll
            for (int e = 0; e < 4; e++) ao[nt][e] = 0.f;

        for (int kt = 0; kt < 14; kt++) {
            float sa[2][4];
#pragma unroll
            for (int ns = 0; ns < 2; ns++)
#pragma unroll
                for (int e = 0; e < 4; e++) sa[ns][e] = 0.f;

#pragma unroll
            for (int ks = 0; ks < 4; ks++) {
#pragma unroll
                for (int ns = 0; ns < 2; ns++) {
                    uint32_t kb[2];
                    uint32_t rowa = (uint32_t)(kt * 16 + ns * 8 + r) * KHW + cg + 8 * ks;
                    kb[0] = lds32(KhU + rowa * 4);
                    kb[1] = lds32(KhU + (rowa + 4) * 4);
                    mma16816(sa[ns], qf[ks], kb);
                }
            }

            float p[2][4];
            float tm0 = -INFINITY, tm1 = -INFINITY;
#pragma unroll
            for (int ns = 0; ns < 2; ns++) {
                int c0 = kt * 16 + ns * 8 + 2 * cg;
                float f0 = fac[c0], f1 = fac[c0 + 1];
                float n0 = nb[c0],  n1 = nb[c0 + 1];
                sa[ns][0] = sa[ns][0] * f0 + n0;
                sa[ns][1] = sa[ns][1] * f1 + n1;
                sa[ns][2] = sa[ns][2] * f0 + n0;
                sa[ns][3] = sa[ns][3] * f1 + n1;
                tm0 = fmaxf(tm0, fmaxf(sa[ns][0], sa[ns][1]));
                tm1 = fmaxf(tm1, fmaxf(sa[ns][2], sa[ns][3]));
            }
#pragma unroll
            for (int o = 1; o <= 2; o <<= 1) {
                tm0 = fmaxf(tm0, __shfl_xor_sync(0xffffffffu, tm0, o));
                tm1 = fmaxf(tm1, __shfl_xor_sync(0xffffffffu, tm1, o));
            }
            float mn0 = fmaxf(m0, tm0), mn1 = fmaxf(m1, tm1);
            float sc0 = __expf(m0 - mn0), sc1 = __expf(m1 - mn1);
            float rs0 = 0.f, rs1 = 0.f;
#pragma unroll
            for (int ns = 0; ns < 2; ns++) {
                p[ns][0] = __expf(sa[ns][0] - mn0);
                p[ns][1] = __expf(sa[ns][1] - mn0);
                p[ns][2] = __expf(sa[ns][2] - mn1);
                p[ns][3] = __expf(sa[ns][3] - mn1);
                rs0 += p[ns][0] + p[ns][1];
                rs1 += p[ns][2] + p[ns][3];
            }
#pragma unroll
            for (int o = 1; o <= 2; o <<= 1) {
                rs0 += __shfl_xor_sync(0xffffffffu, rs0, o);
                rs1 += __shfl_xor_sync(0xffffffffu, rs1, o);
            }
            l0 = l0 * sc0 + rs0; l1 = l1 * sc1 + rs1;
            m0 = mn0; m1 = mn1;

            uint32_t pf[4];
            __half2 ph;
            ph = __floats2half2_rn(p[0][0], p[0][1]); pf[0] = *(uint32_t*)&ph;
            ph = __floats2half2_rn(p[0][2], p[0][3]); pf[1] = *(uint32_t*)&ph;
            ph = __floats2half2_rn(p[1][0], p[1][1]); pf[2] = *(uint32_t*)&ph;
            ph = __floats2half2_rn(p[1][2], p[1][3]); pf[3] = *(uint32_t*)&ph;

#pragma unroll
            for (int nt = 0; nt < 8; nt++) {
                ao[nt][0] *= sc0; ao[nt][1] *= sc0;
                ao[nt][2] *= sc1; ao[nt][3] *= sc1;
                uint32_t vb[2];
                uint32_t rowa = (uint32_t)(nt * 8 + r) * VTW + kt * 8 + cg;
                vb[0] = lds32(VtU + rowa * 4);
                vb[1] = lds32(VtU + (rowa + 4) * 4);
                mma16816(ao[nt], pf, vb);
            }
        }

        float inv0 = 1.f / l0, inv1 = 1.f / l1;
        int q = q0 + r;
        if (q < SS) {
            __half* orow = outp + (size_t)(b * SS + q) * EE + h * HD;
#pragma unroll
            for (int nt = 0; nt < 8; nt++)
                *(__half2*)&orow[nt * 8 + 2 * cg] =
                    __floats2half2_rn(ao[nt][0] * inv0, ao[nt][1] * inv0);
        }
        int q2 = q0 + 8 + r;
        if (q2 < SS) {
            __half* orow = outp + (size_t)(b * SS + q2) * EE + h * HD;
#pragma unroll
            for (int nt = 0; nt < 8; nt++)
                *(__half2*)&orow[nt * 8 + 2 * cg] =
                    __floats2half2_rn(ao[nt][2] * inv1, ao[nt][3] * inv1);
        }
    }
}

// ---------------- host launch ----------------
extern "C" void kernel_launch(void* const* d_in, const int* in_sizes, int n_in,
                              void* d_out, int out_size)
{
    const float* x        = (const float*)d_in[0];
    const float* coeff    = (const float*)d_in[1];
    const float* patch_w  = (const float*)d_in[2];
    const float* patch_b  = (const float*)d_in[3];
    const float* cls      = (const float*)d_in[4];
    const float* pos      = (const float*)d_in[5];
    const float* lnpre_g  = (const float*)d_in[6];
    const float* lnpre_b  = (const float*)d_in[7];
    const float* prompts  = (const float*)d_in[8];
    const float* ln1_g    = (const float*)d_in[9];
    const float* ln1_b    = (const float*)d_in[10];
    const float* qkv_w    = (const float*)d_in[11];
    const float* qkv_b    = (const float*)d_in[12];
    const float* proj_w   = (const float*)d_in[13];
    const float* proj_b   = (const float*)d_in[14];
    const float* ln2_g    = (const float*)d_in[15];
    const float* ln2_b    = (const float*)d_in[16];
    const float* fc1_w    = (const float*)d_in[17];
    const float* fc1_b    = (const float*)d_in[18];
    const float* fc2_w    = (const float*)d_in[19];
    const float* fc2_b    = (const float*)d_in[20];
    const float* lnpost_g = (const float*)d_in[21];
    const float* lnpost_b = (const float*)d_in[22];
    float* out = (float*)d_out;

    float *p_h, *p_o;
    __half *p_hh, *p_qkvh, *p_oh, *p_ffh, *p_wq, *p_wp, *p_w1, *p_w2, *p_wc;
    cudaGetSymbolAddress((void**)&p_h,    g_h);
    cudaGetSymbolAddress((void**)&p_hh,   g_hh);
    cudaGetSymbolAddress((void**)&p_qkvh, g_qkvh);
    cudaGetSymbolAddress((void**)&p_oh,   g_oh);
    cudaGetSymbolAddress((void**)&p_ffh,  g_ffh);
    cudaGetSymbolAddress((void**)&p_o,    g_o);
    cudaGetSymbolAddress((void**)&p_wq,   g_wq);
    cudaGetSymbolAddress((void**)&p_wp,   g_wp);
    cudaGetSymbolAddress((void**)&p_w1,   g_w1);
    cudaGetSymbolAddress((void**)&p_w2,   g_w2);
    cudaGetSymbolAddress((void**)&p_wc,   g_wc);

    cudaFuncSetAttribute(attn_kernel, cudaFuncAttributeMaxDynamicSharedMemorySize, AT_SMEM);
    cudaFuncSetAttribute(hgemm_kernel, cudaFuncAttributeMaxDynamicSharedMemorySize, TG_SMEM);

    {
        int n;
        n = NL * 3 * EE * EE / 4; cvt_kernel<<<(n + 255) / 256, 256>>>(qkv_w,  p_wq, n);
        n = NL * EE * EE / 4;     cvt_kernel<<<(n + 255) / 256, 256>>>(proj_w, p_wp, n);
        n = NL * FFD * EE / 4;    cvt_kernel<<<(n + 255) / 256, 256>>>(fc1_w,  p_w1, n);
        n = NL * EE * FFD / 4;    cvt_kernel<<<(n + 255) / 256, 256>>>(fc2_w,  p_w2, n);
        n = EE * EE / 4;          cvt_kernel<<<(n + 255) / 256, 256>>>(patch_w, p_wc, n);
    }

    im2col_kernel<<<(MCONV * EE + 255) / 256, 256>>>(x, p_ffh);
    hgemm_kernel<<<dim3(EE / 128, MCONV / 128), 256, TG_SMEM>>>(
        p_ffh, p_wc, patch_b, p_o, (__half*)0, MCONV, EE, EE, 0);

    lnpre_kernel<<<BB * NP, 256>>>(p_o, cls, pos, lnpre_g, lnpre_b, p_h);

    const int mt = (BS + 127) / 128;   // 54
    for (int l = 0; l < NL; l++) {
        ln1_kernel<<<BS, 256>>>(p_h, prompts + (size_t)l * NPR * EE,
                                ln1_g + l * EE, ln1_b + l * EE, p_h, p_hh);
        hgemm_kernel<<<dim3(3 * EE / 128, mt), 256, TG_SMEM>>>(
            p_hh, p_wq + (size_t)l * 3 * EE * EE, qkv_b + (size_t)l * 3 * EE,
            (float*)0, p_qkvh, BS, 3 * EE, EE, 3);
        attn_kernel<<<BB * NH, 256, AT_SMEM>>>(p_qkvh, coeff + (size_t)l * NPR, p_oh);
        hgemm_kernel<<<dim3(EE / 128, mt), 256, TG_SMEM>>>(
            p_oh, p_wp + (size_t)l * EE * EE, proj_b + (size_t)l * EE,
            p_h, (__half*)0, BS, EE, EE, 2);
        ln_kernel<<<BS, 256>>>(p_h, ln2_g + l * EE, ln2_b + l * EE, p_hh);
        hgemm_kernel<<<dim3(FFD / 128, mt), 256, TG_SMEM>>>(
            p_hh, p_w1 + (size_t)l * FFD * EE, fc1_b + (size_t)l * FFD,
            (float*)0, p_ffh, BS, FFD, EE, 1);
        hgemm_kernel<<<dim3(EE / 128, mt), 256, TG_SMEM>>>(
            p_ffh, p_w2 + (size_t)l * EE * FFD, fc2_b + (size_t)l * EE,
            p_h, (__half*)0, BS, EE, FFD, 2);
    }

    lnpost_kernel<<<BB, 256>>>(p_h, lnpost_g, lnpost_b, out);
}

// round 13
// speedup vs baseline: 8.1771x; 1.0438x over previous
#include <cuda_runtime.h>
#include <cuda_fp16.h>
#include <math.h>
#include <stdint.h>

// ---------------- geometry ----------------
#define BB     32
#define CCH    3
#define IMG    224
#define PTCH   16
#define EE     768
#define NH     12
#define NL     12
#define NPR    16
#define NP     197
#define SS     213
#define HD     64
#define FFD    3072
#define EPSV   1e-6f
#define SCALEV 0.125f

#define BS      (BB * SS)          // 6816
#define NPATCH  196
#define MCONV   (BB * NPATCH)      // 6272
#define QPLANE  ((size_t)BB * NH * SS * HD)   // halfs per q/k/v plane

// ---------------- scratch (device globals: allowed) ----------------
__device__ float  g_h  [(size_t)BS * EE];          // fp32 residual stream
__device__ __half g_hh [(size_t)BS * EE];          // LN outputs (half)
__device__ __half g_qs [3 * QPLANE];               // qkv head-separated planes
__device__ __half g_oh [(size_t)BS * EE];          // attention out (half)
__device__ __half g_ffh[(size_t)BS * FFD];         // fc1 out / im2col (half)
__device__ float  g_o  [(size_t)BS * EE];          // conv out (fp32)
// fp16 weight copies
__device__ __half g_wq [(size_t)NL * 3 * EE * EE];
__device__ __half g_wp [(size_t)NL * EE * EE];
__device__ __half g_w1 [(size_t)NL * FFD * EE];
__device__ __half g_w2 [(size_t)NL * EE * FFD];
__device__ __half g_wc [(size_t)EE * EE];

// ---------------- helpers ----------------
__device__ __forceinline__ float blk_sum(float v) {
    __shared__ float red[8];
    __shared__ float tot;
    int lane = threadIdx.x & 31, w = threadIdx.x >> 5;
#pragma unroll
    for (int o = 16; o; o >>= 1) v += __shfl_xor_sync(0xffffffffu, v, o);
    if (lane == 0) red[w] = v;
    __syncthreads();
    if (w == 0) {
        float t = (lane < 8) ? red[lane] : 0.f;
#pragma unroll
        for (int o = 4; o; o >>= 1) t += __shfl_xor_sync(0xffffffffu, t, o);
        if (lane == 0) tot = t;
    }
    __syncthreads();
    return tot;
}

__device__ __forceinline__ void cpa16_s(uint32_t dst, const void* src, int srcBytes) {
    asm volatile("cp.async.cg.shared.global [%0], [%1], 16, %2;"
                 :: "r"(dst), "l"(src), "r"(srcBytes));
}

__device__ __forceinline__ void ldsm4(uint32_t* d, uint32_t addr) {
    asm volatile("ldmatrix.sync.aligned.m8n8.x4.shared.b16 {%0,%1,%2,%3}, [%4];"
                 : "=r"(d[0]), "=r"(d[1]), "=r"(d[2]), "=r"(d[3]) : "r"(addr));
}

__device__ __forceinline__ void ldsm4t(uint32_t* d, uint32_t addr) {
    asm volatile("ldmatrix.sync.aligned.m8n8.x4.trans.shared.b16 {%0,%1,%2,%3}, [%4];"
                 : "=r"(d[0]), "=r"(d[1]), "=r"(d[2]), "=r"(d[3]) : "r"(addr));
}

__device__ __forceinline__ void mma16816(float* d, const uint32_t* a, const uint32_t* b) {
    asm volatile(
        "mma.sync.aligned.m16n8k16.row.col.f32.f16.f16.f32 "
        "{%0,%1,%2,%3}, {%4,%5,%6,%7}, {%8,%9}, {%0,%1,%2,%3};"
        : "+f"(d[0]), "+f"(d[1]), "+f"(d[2]), "+f"(d[3])
        : "r"(a[0]), "r"(a[1]), "r"(a[2]), "r"(a[3]), "r"(b[0]), "r"(b[1]));
}

// ---------------- weight fp16 convert ----------------
__global__ void cvt_kernel(const float* __restrict__ src, __half* __restrict__ dst, int n4) {
    int i = blockIdx.x * 256 + threadIdx.x;
    if (i >= n4) return;
    float4 v = ((const float4*)src)[i];
    ((__half2*)dst)[2 * i]     = __floats2half2_rn(v.x, v.y);
    ((__half2*)dst)[2 * i + 1] = __floats2half2_rn(v.z, v.w);
}

// ---------------- im2col (half out) ----------------
__global__ void im2col_kernel(const float* __restrict__ x, __half* __restrict__ out) {
    int idx = blockIdx.x * 256 + threadIdx.x;
    if (idx >= MCONV * EE) return;
    int m = idx / EE;
    int k = idx % EE;
    int b = m / NPATCH, p = m % NPATCH;
    int c = k >> 8, rem = k & 255, i = rem >> 4, j = rem & 15;
    int py = p / 14, px = p % 14;
    out[idx] = __float2half_rn(
        x[(((size_t)b * CCH + c) * IMG + (py * PTCH + i)) * IMG + (px * PTCH + j)]);
}

// ---------------- FP16 tensor GEMM (mma.sync m16n8k16 + ldmatrix) ----------
// epi 0: fp32 out ; epi 1: bias+GELU -> half ; epi 2: bias+residual fp32 ;
// epi 3: bias -> half ; epi 4: bias -> half, qkv head-separated planes
#define KT        64
#define RSB       144
#define MAT_BYTES (128 * RSB)
#define STG_BYTES (2 * MAT_BYTES)
#define NSTAGE    3
#define TG_SMEM   (NSTAGE * STG_BYTES)

__global__ __launch_bounds__(256)
void hgemm_kernel(const __half* __restrict__ A, const __half* __restrict__ Bw,
                  const float* __restrict__ bias, float* __restrict__ Cf,
                  __half* __restrict__ Ch, int M, int N, int K, int epi)
{
    extern __shared__ char smg[];
    const uint32_t smem_base = (uint32_t)__cvta_generic_to_shared(smg);
    const int tid  = threadIdx.x;
    const int warp = tid >> 5, lane = tid & 31;
    const int wm = warp >> 2;
    const int wn = warp & 3;
    const int r  = lane >> 2;
    const int cg = lane & 3;
    const int row0 = blockIdx.y * 128;
    const int col0 = blockIdx.x * 128;

    const int lg = lane >> 3;
    const int lt = lane & 7;

    float acc[4][4][4];
#pragma unroll
    for (int mi = 0; mi < 4; mi++)
#pragma unroll
        for (int ni = 0; ni < 4; ni++)
#pragma unroll
            for (int e = 0; e < 4; e++) acc[mi][ni][e] = 0.f;

    const int frow   = tid >> 3;
    const int fcol16 = tid & 7;
    const int nc = K / KT;

#define FILL(sidx, kk0)                                                          \
    {                                                                            \
        uint32_t sA = smem_base + (sidx) * STG_BYTES;                            \
        uint32_t sB = sA + MAT_BYTES;                                            \
        _Pragma("unroll")                                                        \
        for (int c = 0; c < 4; c++) {                                            \
            int row = frow + c * 32;                                             \
            uint32_t doff = (uint32_t)row * RSB + fcol16 * 16;                   \
            cpa16_s(sA + doff, A + (size_t)(row0 + row) * K + (kk0) + fcol16 * 8,\
                    (row0 + row < M) ? 16 : 0);                                  \
            cpa16_s(sB + doff, Bw + (size_t)(col0 + row) * K + (kk0) + fcol16 * 8, 16);\
        }                                                                        \
        asm volatile("cp.async.commit_group;");                                  \
    }

    FILL(0, 0);
    if (nc > 1) FILL(1, KT);

    for (int i = 0; i < nc; i++) {
        if (i + 1 < nc) {
            asm volatile("cp.async.wait_group 1;");
        } else {
            asm volatile("cp.async.wait_group 0;");
        }
        __syncthreads();
        if (i + 2 < nc) FILL((i + 2) % NSTAGE, (i + 2) * KT);

        const uint32_t sA = smem_base + (i % NSTAGE) * STG_BYTES;
        const uint32_t sB = sA + MAT_BYTES;
#pragma unroll
        for (int kk = 0; kk < KT; kk += 16) {
            uint32_t af[4][4], bB[2][4];
#pragma unroll
            for (int mi = 0; mi < 4; mi++) {
                uint32_t addr = sA
                    + (uint32_t)(wm * 64 + mi * 16 + (lg & 1) * 8 + lt) * RSB
                    + (kk + (lg >> 1) * 8) * 2;
                ldsm4(af[mi], addr);
            }
#pragma unroll
            for (int ni2 = 0; ni2 < 2; ni2++) {
                uint32_t addr = sB
                    + (uint32_t)(wn * 32 + ni2 * 16 + (lg >> 1) * 8 + lt) * RSB
                    + (kk + (lg & 1) * 8) * 2;
                ldsm4(bB[ni2], addr);
            }
#pragma unroll
            for (int mi = 0; mi < 4; mi++)
#pragma unroll
                for (int ni = 0; ni < 4; ni++)
                    mma16816(acc[mi][ni], af[mi], &bB[ni >> 1][(ni & 1) * 2]);
        }
    }
#undef FILL

#pragma unroll
    for (int mi = 0; mi < 4; mi++) {
        int mr0 = row0 + wm * 64 + mi * 16 + r;
#pragma unroll
        for (int ni = 0; ni < 4; ni++) {
            int nc2 = col0 + wn * 32 + ni * 8 + 2 * cg;
            float b0 = bias[nc2], b1 = bias[nc2 + 1];
#pragma unroll
            for (int half_ = 0; half_ < 2; half_++) {
                int rr = mr0 + half_ * 8;
                if (rr >= M) continue;
                float v0 = acc[mi][ni][half_ * 2 + 0] + b0;
                float v1 = acc[mi][ni][half_ * 2 + 1] + b1;
                size_t idx = (size_t)rr * N + nc2;
                if (epi == 1) {
                    v0 = 0.5f * v0 * (1.f + erff(v0 * 0.70710678118654752f));
                    v1 = 0.5f * v1 * (1.f + erff(v1 * 0.70710678118654752f));
                    *(__half2*)&Ch[idx] = __floats2half2_rn(v0, v1);
                } else if (epi == 3) {
                    *(__half2*)&Ch[idx] = __floats2half2_rn(v0, v1);
                } else if (epi == 4) {
                    int b = rr / SS, s = rr % SS;
                    int p = nc2 / EE, e = nc2 - p * EE;
                    int hh = e >> 6, d = e & 63;
                    __half* dst = Ch + (size_t)p * QPLANE
                                + ((size_t)(b * NH + hh) * SS + s) * HD + d;
                    *(__half2*)dst = __floats2half2_rn(v0, v1);
                } else {
                    if (epi == 2) { v0 += Cf[idx]; v1 += Cf[idx + 1]; }
                    Cf[idx] = v0; Cf[idx + 1] = v1;
                }
            }
        }
    }
}

// ---------------- LN pre (cls/pos assembly; fp32 out) ----------------
__global__ void lnpre_kernel(const float* __restrict__ conv, const float* __restrict__ cls,
                             const float* __restrict__ pos, const float* __restrict__ g,
                             const float* __restrict__ bb, float* __restrict__ dst)
{
    int row = blockIdx.x;
    int b = row / NP, s = row % NP;
    int t = threadIdx.x;
    const float* base = (s == 0) ? cls : conv + (size_t)(b * NPATCH + s - 1) * EE;
    const float* pr = pos + (size_t)s * EE;
    float x0 = base[t] + pr[t];
    float x1 = base[t + 256] + pr[t + 256];
    float x2 = base[t + 512] + pr[t + 512];
    float mean = blk_sum(x0 + x1 + x2) * (1.f / EE);
    float d0 = x0 - mean, d1 = x1 - mean, d2 = x2 - mean;
    float var = blk_sum(d0 * d0 + d1 * d1 + d2 * d2) * (1.f / EE);
    float rs = rsqrtf(var + EPSV);
    float* o = dst + (size_t)(b * SS + s) * EE;
    o[t]       = d0 * rs * g[t]       + bb[t];
    o[t + 256] = d1 * rs * g[t + 256] + bb[t + 256];
    o[t + 512] = d2 * rs * g[t + 512] + bb[t + 512];
}

// ---------------- LN1 warp-per-row (prompt substitution; half out) -----------
__global__ __launch_bounds__(256)
void ln1w_kernel(const float* __restrict__ src, const float* __restrict__ prompt,
                 const float* __restrict__ g, const float* __restrict__ bb,
                 float* __restrict__ hwr, __half* __restrict__ dst)
{
    int ww = threadIdx.x >> 5, lane = threadIdx.x & 31;
    int row = blockIdx.x * 8 + ww;            // BS = 852*8 exactly
    int s = row % SS;
    const float* in = (s < NP) ? src + (size_t)row * EE
                               : prompt + (size_t)(s - NP) * EE;
    float4 v[6];
    float sum = 0.f;
#pragma unroll
    for (int j = 0; j < 6; j++) {
        v[j] = *(const float4*)(in + j * 128 + lane * 4);
        sum += v[j].x + v[j].y + v[j].z + v[j].w;
    }
#pragma unroll
    for (int o = 16; o; o >>= 1) sum += __shfl_xor_sync(0xffffffffu, sum, o);
    float mean = sum * (1.f / EE);
    float var = 0.f;
#pragma unroll
    for (int j = 0; j < 6; j++) {
        float a = v[j].x - mean, b2 = v[j].y - mean;
        float c = v[j].z - mean, d = v[j].w - mean;
        var += a * a + b2 * b2 + c * c + d * d;
    }
#pragma unroll
    for (int o = 16; o; o >>= 1) var += __shfl_xor_sync(0xffffffffu, var, o);
    float rs = rsqrtf(var * (1.f / EE) + EPSV);
    if (s >= NP) {
        float* hw = hwr + (size_t)row * EE;
#pragma unroll
        for (int j = 0; j < 6; j++)
            *(float4*)(hw + j * 128 + lane * 4) = v[j];
    }
    __half* op = dst + (size_t)row * EE;
#pragma unroll
    for (int j = 0; j < 6; j++) {
        int e = j * 128 + lane * 4;
        float4 gv = *(const float4*)(g + e);
        float4 bv = *(const float4*)(bb + e);
        float r0 = (v[j].x - mean) * rs * gv.x + bv.x;
        float r1 = (v[j].y - mean) * rs * gv.y + bv.y;
        float r2 = (v[j].z - mean) * rs * gv.z + bv.z;
        float r3 = (v[j].w - mean) * rs * gv.w + bv.w;
        *(__half2*)(op + e)     = __floats2half2_rn(r0, r1);
        *(__half2*)(op + e + 2) = __floats2half2_rn(r2, r3);
    }
}

// ---------------- LN2 warp-per-row (half out) ----------------
__global__ __launch_bounds__(256)
void lnw_kernel(const float* __restrict__ src, const float* __restrict__ g,
                const float* __restrict__ bb, __half* __restrict__ dst)
{
    int ww = threadIdx.x >> 5, lane = threadIdx.x & 31;
    int row = blockIdx.x * 8 + ww;
    const float* in = src + (size_t)row * EE;
    float4 v[6];
    float sum = 0.f;
#pragma unroll
    for (int j = 0; j < 6; j++) {
        v[j] = *(const float4*)(in + j * 128 + lane * 4);
        sum += v[j].x + v[j].y + v[j].z + v[j].w;
    }
#pragma unroll
    for (int o = 16; o; o >>= 1) sum += __shfl_xor_sync(0xffffffffu, sum, o);
    float mean = sum * (1.f / EE);
    float var = 0.f;
#pragma unroll
    for (int j = 0; j < 6; j++) {
        float a = v[j].x - mean, b2 = v[j].y - mean;
        float c = v[j].z - mean, d = v[j].w - mean;
        var += a * a + b2 * b2 + c * c + d * d;
    }
#pragma unroll
    for (int o = 16; o; o >>= 1) var += __shfl_xor_sync(0xffffffffu, var, o);
    float rs = rsqrtf(var * (1.f / EE) + EPSV);
    __half* op = dst + (size_t)row * EE;
#pragma unroll
    for (int j = 0; j < 6; j++) {
        int e = j * 128 + lane * 4;
        float4 gv = *(const float4*)(g + e);
        float4 bv = *(const float4*)(bb + e);
        float r0 = (v[j].x - mean) * rs * gv.x + bv.x;
        float r1 = (v[j].y - mean) * rs * gv.y + bv.y;
        float r2 = (v[j].z - mean) * rs * gv.z + bv.z;
        float r3 = (v[j].w - mean) * rs * gv.w + bv.w;
        *(__half2*)(op + e)     = __floats2half2_rn(r0, r1);
        *(__half2*)(op + e + 2) = __floats2half2_rn(r2, r3);
    }
}

// ---------------- LN post (cls only; fp32 out) ----------------
__global__ void lnpost_kernel(const float* __restrict__ src, const float* __restrict__ g,
                              const float* __restrict__ bb, float* __restrict__ dst)
{
    int b = blockIdx.x;
    int t = threadIdx.x;
    const float* in = src + (size_t)(b * SS) * EE;
    float x0 = in[t], x1 = in[t + 256], x2 = in[t + 512];
    float mean = blk_sum(x0 + x1 + x2) * (1.f / EE);
    float d0 = x0 - mean, d1 = x1 - mean, d2 = x2 - mean;
    float var = blk_sum(d0 * d0 + d1 * d1 + d2 * d2) * (1.f / EE);
    float rs = rsqrtf(var + EPSV);
    float* o = dst + (size_t)b * EE;
    o[t]       = d0 * rs * g[t]       + bb[t];
    o[t + 256] = d1 * rs * g[t + 256] + bb[t + 256];
    o[t + 512] = d2 * rs * g[t + 512] + bb[t + 512];
}

// ---------------- tensor-core flash attention (head-separated planes) -------
// smem: Qv/Kv/Vv each [224][72]h (144B rows), then fac/nb [224]f each
#define ATROW 144
#define ATPL  (224 * ATROW)                  // 32256 B per plane
#define AT_SMEM (3 * ATPL + 224 * 8)

__global__ __launch_bounds__(256)
void attn_kernel(const __half* __restrict__ qsep,
                 const float* __restrict__ coeff,
                 __half* __restrict__ outp)
{
    extern __shared__ char smraw[];
    const uint32_t smem_base = (uint32_t)__cvta_generic_to_shared(smraw);
    float* fac = (float*)(smraw + 3 * ATPL);
    float* nb  = fac + 224;

    const int bh = blockIdx.x;
    const int b = bh / NH, h = bh % NH;
    const int tid = threadIdx.x;
    const int w = tid >> 5, lane = tid & 31;
    const int r = lane >> 2, cg = lane & 3;
    const int lg = lane >> 3, lt = lane & 7;

    const size_t bhbase = (size_t)(b * NH + h) * SS * HD;

    if (tid < 224) {
        float f = 0.f, nbv = -1e30f;
        if (tid < NP)      { f = SCALEV; nbv = 0.f; }
        else if (tid < SS) { f = SCALEV * coeff[tid - NP]; nbv = 0.f; }
        fac[tid] = f; nb[tid] = nbv;
    }
    // stage Q, K, V planes via cp.async (zero-fill past SS)
    for (int idx = tid; idx < 3 * 224 * 8; idx += 256) {
        int pl = idx / (224 * 8);
        int rem = idx - pl * (224 * 8);
        int s = rem >> 3, c = rem & 7;
        const __half* src = qsep + (size_t)pl * QPLANE + bhbase + (size_t)s * HD + c * 8;
        cpa16_s(smem_base + pl * ATPL + s * ATROW + c * 16, src, (s < SS) ? 16 : 0);
    }
    asm volatile("cp.async.commit_group;");
    asm volatile("cp.async.wait_group 0;");
    __syncthreads();

    const uint32_t QvU = smem_base;
    const uint32_t KvU = smem_base + ATPL;
    const uint32_t VvU = smem_base + 2 * ATPL;

    for (int q0 = w * 16; q0 < 224; q0 += 128) {
        uint32_t qf[4][4];
#pragma unroll
        for (int ks = 0; ks < 4; ks++)
            ldsm4(qf[ks], QvU + (uint32_t)(q0 + (lg & 1) * 8 + lt) * ATROW
                              + (ks * 16 + (lg >> 1) * 8) * 2);

        float m0 = -INFINITY, m1 = -INFINITY, l0 = 0.f, l1 = 0.f;
        float ao[8][4];
#pragma unroll
        for (int nt = 0; nt < 8; nt++)
#pragma unroll
            for (int e = 0; e < 4; e++) ao[nt][e] = 0.f;

        for (int kt = 0; kt < 14; kt++) {
            float sa[2][4];
#pragma unroll
            for (int ns = 0; ns < 2; ns++)
#pragma unroll
                for (int e = 0; e < 4; e++) sa[ns][e] = 0.f;

#pragma unroll
            for (int ks = 0; ks < 4; ks++) {
                uint32_t bK[4];
                ldsm4(bK, KvU + (uint32_t)(kt * 16 + (lg >> 1) * 8 + lt) * ATROW
                              + (ks * 16 + (lg & 1) * 8) * 2);
                mma16816(sa[0], qf[ks], &bK[0]);
                mma16816(sa[1], qf[ks], &bK[2]);
            }

            float p[2][4];
            float tm0 = -INFINITY, tm1 = -INFINITY;
#pragma unroll
            for (int ns = 0; ns < 2; ns++) {
                int c0 = kt * 16 + ns * 8 + 2 * cg;
                float f0 = fac[c0], f1 = fac[c0 + 1];
                float n0 = nb[c0],  n1 = nb[c0 + 1];
                sa[ns][0] = sa[ns][0] * f0 + n0;
                sa[ns][1] = sa[ns][1] * f1 + n1;
                sa[ns][2] = sa[ns][2] * f0 + n0;
                sa[ns][3] = sa[ns][3] * f1 + n1;
                tm0 = fmaxf(tm0, fmaxf(sa[ns][0], sa[ns][1]));
                tm1 = fmaxf(tm1, fmaxf(sa[ns][2], sa[ns][3]));
            }
#pragma unroll
            for (int o = 1; o <= 2; o <<= 1) {
                tm0 = fmaxf(tm0, __shfl_xor_sync(0xffffffffu, tm0, o));
                tm1 = fmaxf(tm1, __shfl_xor_sync(0xffffffffu, tm1, o));
            }
            float mn0 = fmaxf(m0, tm0), mn1 = fmaxf(m1, tm1);
            float sc0 = __expf(m0 - mn0), sc1 = __expf(m1 - mn1);
            float rs0 = 0.f, rs1 = 0.f;
#pragma unroll
            for (int ns = 0; ns < 2; ns++) {
                p[ns][0] = __expf(sa[ns][0] - mn0);
                p[ns][1] = __expf(sa[ns][1] - mn0);
                p[ns][2] = __expf(sa[ns][2] - mn1);
                p[ns][3] = __expf(sa[ns][3] - mn1);
                rs0 += p[ns][0] + p[ns][1];
                rs1 += p[ns][2] + p[ns][3];
            }
#pragma unroll
            for (int o = 1; o <= 2; o <<= 1) {
                rs0 += __shfl_xor_sync(0xffffffffu, rs0, o);
                rs1 += __shfl_xor_sync(0xffffffffu, rs1, o);
            }
            l0 = l0 * sc0 + rs0; l1 = l1 * sc1 + rs1;
            m0 = mn0; m1 = mn1;

            uint32_t pf[4];
            __half2 ph;
            ph = __floats2half2_rn(p[0][0], p[0][1]); pf[0] = *(uint32_t*)&ph;
            ph = __floats2half2_rn(p[0][2], p[0][3]); pf[1] = *(uint32_t*)&ph;
            ph = __floats2half2_rn(p[1][0], p[1][1]); pf[2] = *(uint32_t*)&ph;
            ph = __floats2half2_rn(p[1][2], p[1][3]); pf[3] = *(uint32_t*)&ph;

#pragma unroll
            for (int nt2 = 0; nt2 < 4; nt2++) {
                uint32_t vf[4];
                ldsm4t(vf, VvU + (uint32_t)(kt * 16 + (lg & 1) * 8 + lt) * ATROW
                               + (nt2 * 16 + (lg >> 1) * 8) * 2);
                int n0 = 2 * nt2, n1 = 2 * nt2 + 1;
                ao[n0][0] *= sc0; ao[n0][1] *= sc0; ao[n0][2] *= sc1; ao[n0][3] *= sc1;
                ao[n1][0] *= sc0; ao[n1][1] *= sc0; ao[n1][2] *= sc1; ao[n1][3] *= sc1;
                mma16816(ao[n0], pf, &vf[0]);
                mma16816(ao[n1], pf, &vf[2]);
            }
        }

        float inv0 = 1.f / l0, inv1 = 1.f / l1;
        int q = q0 + r;
        if (q < SS) {
            __half* orow = outp + (size_t)(b * SS + q) * EE + h * HD;
#pragma unroll
            for (int nt = 0; nt < 8; nt++)
                *(__half2*)&orow[nt * 8 + 2 * cg] =
                    __floats2half2_rn(ao[nt][0] * inv0, ao[nt][1] * inv0);
        }
        int q2 = q0 + 8 + r;
        if (q2 < SS) {
            __half* orow = outp + (size_t)(b * SS + q2) * EE + h * HD;
#pragma unroll
            for (int nt = 0; nt < 8; nt++)
                *(__half2*)&orow[nt * 8 + 2 * cg] =
                    __floats2half2_rn(ao[nt][2] * inv1, ao[nt][3] * inv1);
        }
    }
}

// ---------------- host launch ----------------
extern "C" void kernel_launch(void* const* d_in, const int* in_sizes, int n_in,
                              void* d_out, int out_size)
{
    const float* x        = (const float*)d_in[0];
    const float* coeff    = (const float*)d_in[1];
    const float* patch_w  = (const float*)d_in[2];
    const float* patch_b  = (const float*)d_in[3];
    const float* cls      = (const float*)d_in[4];
    const float* pos      = (const float*)d_in[5];
    const float* lnpre_g  = (const float*)d_in[6];
    const float* lnpre_b  = (const float*)d_in[7];
    const float* prompts  = (const float*)d_in[8];
    const float* ln1_g    = (const float*)d_in[9];
    const float* ln1_b    = (const float*)d_in[10];
    const float* qkv_w    = (const float*)d_in[11];
    const float* qkv_b    = (const float*)d_in[12];
    const float* proj_w   = (const float*)d_in[13];
    const float* proj_b   = (const float*)d_in[14];
    const float* ln2_g    = (const float*)d_in[15];
    const float* ln2_b    = (const float*)d_in[16];
    const float* fc1_w    = (const float*)d_in[17];
    const float* fc1_b    = (const float*)d_in[18];
    const float* fc2_w    = (const float*)d_in[19];
    const float* fc2_b    = (const float*)d_in[20];
    const float* lnpost_g = (const float*)d_in[21];
    const float* lnpost_b = (const float*)d_in[22];
    float* out = (float*)d_out;

    float *p_h, *p_o;
    __half *p_hh, *p_qs, *p_oh, *p_ffh, *p_wq, *p_wp, *p_w1, *p_w2, *p_wc;
    cudaGetSymbolAddress((void**)&p_h,   g_h);
    cudaGetSymbolAddress((void**)&p_hh,  g_hh);
    cudaGetSymbolAddress((void**)&p_qs,  g_qs);
    cudaGetSymbolAddress((void**)&p_oh,  g_oh);
    cudaGetSymbolAddress((void**)&p_ffh, g_ffh);
    cudaGetSymbolAddress((void**)&p_o,   g_o);
    cudaGetSymbolAddress((void**)&p_wq,  g_wq);
    cudaGetSymbolAddress((void**)&p_wp,  g_wp);
    cudaGetSymbolAddress((void**)&p_w1,  g_w1);
    cudaGetSymbolAddress((void**)&p_w2,  g_w2);
    cudaGetSymbolAddress((void**)&p_wc,  g_wc);

    cudaFuncSetAttribute(attn_kernel, cudaFuncAttributeMaxDynamicSharedMemorySize, AT_SMEM);
    cudaFuncSetAttribute(hgemm_kernel, cudaFuncAttributeMaxDynamicSharedMemorySize, TG_SMEM);

    {
        int n;
        n = NL * 3 * EE * EE / 4; cvt_kernel<<<(n + 255) / 256, 256>>>(qkv_w,  p_wq, n);
        n = NL * EE * EE / 4;     cvt_kernel<<<(n + 255) / 256, 256>>>(proj_w, p_wp, n);
        n = NL * FFD * EE / 4;    cvt_kernel<<<(n + 255) / 256, 256>>>(fc1_w,  p_w1, n);
        n = NL * EE * FFD / 4;    cvt_kernel<<<(n + 255) / 256, 256>>>(fc2_w,  p_w2, n);
        n = EE * EE / 4;          cvt_kernel<<<(n + 255) / 256, 256>>>(patch_w, p_wc, n);
    }

    im2col_kernel<<<(MCONV * EE + 255) / 256, 256>>>(x, p_ffh);
    hgemm_kernel<<<dim3(EE / 128, MCONV / 128), 256, TG_SMEM>>>(
        p_ffh, p_wc, patch_b, p_o, (__half*)0, MCONV, EE, EE, 0);

    lnpre_kernel<<<BB * NP, 256>>>(p_o, cls, pos, lnpre_g, lnpre_b, p_h);

    const int mt = (BS + 127) / 128;   // 54
    for (int l = 0; l < NL; l++) {
        ln1w_kernel<<<BS / 8, 256>>>(p_h, prompts + (size_t)l * NPR * EE,
                                     ln1_g + l * EE, ln1_b + l * EE, p_h, p_hh);
        hgemm_kernel<<<dim3(3 * EE / 128, mt), 256, TG_SMEM>>>(
            p_hh, p_wq + (size_t)l * 3 * EE * EE, qkv_b + (size_t)l * 3 * EE,
            (float*)0, p_qs, BS, 3 * EE, EE, 4);
        attn_kernel<<<BB * NH, 256, AT_SMEM>>>(p_qs, coeff + (size_t)l * NPR, p_oh);
        hgemm_kernel<<<dim3(EE / 128, mt), 256, TG_SMEM>>>(
            p_oh, p_wp + (size_t)l * EE * EE, proj_b + (size_t)l * EE,
            p_h, (__half*)0, BS, EE, EE, 2);
        lnw_kernel<<<BS / 8, 256>>>(p_h, ln2_g + l * EE, ln2_b + l * EE, p_hh);
        hgemm_kernel<<<dim3(FFD / 128, mt), 256, TG_SMEM>>>(
            p_hh, p_w1 + (size_t)l * FFD * EE, fc1_b + (size_t)l * FFD,
            (float*)0, p_ffh, BS, FFD, EE, 1);
        hgemm_kernel<<<dim3(EE / 128, mt), 256, TG_SMEM>>>(
            p_ffh, p_w2 + (size_t)l * EE * FFD, fc2_b + (size_t)l * EE,
            p_h, (__half*)0, BS, EE, FFD, 2);
    }

    lnpost_kernel<<<BB, 256>>>(p_h, lnpost_g, lnpost_b, out);
}